// round 2
// baseline (speedup 1.0000x reference)
#include <cuda_runtime.h>

// ---------------------------------------------------------------------------
// EGNN layer: N=20000 nodes, E=320000 edges, H=256.
//   edge MLP: [E,513] @ [513,256] -> silu -> @ [256,256] -> silu = m_ij
//   coord:    silu(m_ij @ [256,256]) @ [256,1] -> scatter(w*diff, col)
//   msg:      scatter(m_ij, col)
//   node MLP: [N,512] @ [512,256] -> silu -> @ [256,256] ; +h ; LayerNorm
// Strategy: 32-edge (32-node) tiles per block, 256 threads = one output
// feature each, 32 fp32 register accumulators, k-major SMEM staging with
// stride 36 floats (16B aligned for LDS.128, <=4-way bank conflicts).
// edge_index dtype (int32 vs int64) detected at runtime (JAX x64 ambiguity).
// ---------------------------------------------------------------------------

#define HDIM    256
#define NNODE   20000
#define NEDGE   320000
#define TILE    32
#define NTHR    256
#define STR     36          // smem row stride in floats (144B, 16B aligned)
#define LN_EPS  1e-5f

// scratch (device globals: allocation-free per harness rules)
__device__ float g_msg[NNODE * HDIM];     // 20.5 MB
__device__ float g_coord[NNODE * 3];
__device__ int   g_is64;                  // 1 if edge_index is int64

__device__ __forceinline__ float silu_f(float v) {
    return v / (1.0f + __expf(-v));
}

// ---------------------------------------------------------------------------
// Detect edge_index dtype. Reads only the first 8KB of the buffer (safe for
// both int32 [2.56MB] and int64 [5.12MB] layouts). int64 node indices are
// < 20000, so every high 32-bit word is zero; int32 layout puts real indices
// at odd word positions (all-zero probability ~ (1/20000)^1000).
// ---------------------------------------------------------------------------
__global__ void detect_kernel(const unsigned* __restrict__ w) {
    unsigned acc = 0;
    for (int i = threadIdx.x; i < 1024; i += 32) acc |= w[2 * i + 1];
    #pragma unroll
    for (int o = 16; o; o >>= 1) acc |= __shfl_xor_sync(0xFFFFFFFFu, acc, o);
    if (threadIdx.x == 0) g_is64 = (acc == 0) ? 1 : 0;
}

// ---------------------------------------------------------------------------
__global__ void zero_kernel() {
    int i = blockIdx.x * blockDim.x + threadIdx.x;
    int stride = gridDim.x * blockDim.x;
    for (int idx = i; idx < NNODE * HDIM; idx += stride) g_msg[idx] = 0.0f;
    for (int idx = i; idx < NNODE * 3;    idx += stride) g_coord[idx] = 0.0f;
}

// ---------------------------------------------------------------------------
// Edge kernel: one block = 32 edges. Thread tid owns output feature j = tid.
// ---------------------------------------------------------------------------
extern __shared__ float smem_e[];

__global__ __launch_bounds__(NTHR, 2)
void edge_kernel(const float* __restrict__ h, const float* __restrict__ x,
                 const void* __restrict__ ei_raw,
                 const float* __restrict__ W1, const float* __restrict__ b1,
                 const float* __restrict__ W2, const float* __restrict__ b2,
                 const float* __restrict__ C1, const float* __restrict__ cb1,
                 const float* __restrict__ C2)
{
    // smem layout (floats)
    float* s_in   = smem_e;                 // 513 * 36 = 18468 (k-major edge_input)
    float* s_m    = s_in + 513 * STR;       // 256 * 36 =  9216 (k-major m)
    float* s_diff = s_m + 256 * STR;        // 96
    float* s_red  = s_diff + 96;            // 256
    int*   s_row  = (int*)(s_red + 256);    // 32
    int*   s_col  = s_row + 32;             // 32
    float* s_mij  = s_in;                   // alias: s_in dead after phase B

    const int tid = threadIdx.x;
    const int e0  = blockIdx.x * TILE;

    if (tid < TILE) {
        int e = e0 + tid;
        int r, c;
        if (g_is64) {
            const long long* p = (const long long*)ei_raw;
            r = (int)p[e];
            c = (int)p[NEDGE + e];
        } else {
            const int* p = (const int*)ei_raw;
            r = p[e];
            c = p[NEDGE + e];
        }
        s_row[tid] = r;
        s_col[tid] = c;
        float dx = x[r * 3 + 0] - x[c * 3 + 0];
        float dy = x[r * 3 + 1] - x[c * 3 + 1];
        float dz = x[r * 3 + 2] - x[c * 3 + 2];
        s_diff[tid * 3 + 0] = dx;
        s_diff[tid * 3 + 1] = dy;
        s_diff[tid * 3 + 2] = dz;
        s_in[512 * STR + tid] = dx * dx + dy * dy + dz * dz;   // dist_sq row
    }
    __syncthreads();

    // stage edge_input[k][e]: k<256 -> h[row], k in [256,512) -> h[col]
    for (int idx = tid; idx < TILE * 512; idx += NTHR) {
        int e = idx >> 9;          // /512
        int k = idx & 511;
        int node = (k < HDIM) ? s_row[e] : s_col[e];
        s_in[k * STR + e] = h[node * HDIM + (k & (HDIM - 1))];
    }
    __syncthreads();

    float acc[TILE];

    // ---- phase B: m = silu(edge_input @ W1 + b1) ----
    {
        float bj = b1[tid];
        #pragma unroll
        for (int e = 0; e < TILE; e++) acc[e] = bj;
        for (int k = 0; k < 512; k++) {
            float w = W1[k * HDIM + tid];
            const float4* v4 = reinterpret_cast<const float4*>(&s_in[k * STR]);
            #pragma unroll
            for (int q = 0; q < 8; q++) {
                float4 v = v4[q];
                acc[4 * q + 0] = fmaf(v.x, w, acc[4 * q + 0]);
                acc[4 * q + 1] = fmaf(v.y, w, acc[4 * q + 1]);
                acc[4 * q + 2] = fmaf(v.z, w, acc[4 * q + 2]);
                acc[4 * q + 3] = fmaf(v.w, w, acc[4 * q + 3]);
            }
        }
        // dist_sq term (k = 512)
        float wd = W1[512 * HDIM + tid];
        const float4* d4 = reinterpret_cast<const float4*>(&s_in[512 * STR]);
        #pragma unroll
        for (int q = 0; q < 8; q++) {
            float4 v = d4[q];
            acc[4 * q + 0] = fmaf(v.x, wd, acc[4 * q + 0]);
            acc[4 * q + 1] = fmaf(v.y, wd, acc[4 * q + 1]);
            acc[4 * q + 2] = fmaf(v.z, wd, acc[4 * q + 2]);
            acc[4 * q + 3] = fmaf(v.w, wd, acc[4 * q + 3]);
        }
        #pragma unroll
        for (int e = 0; e < TILE; e++) s_m[tid * STR + e] = silu_f(acc[e]);
    }
    __syncthreads();

    // ---- phase D: m_ij = silu(m @ W2 + b2); scatter to g_msg ----
    {
        float bj = b2[tid];
        #pragma unroll
        for (int e = 0; e < TILE; e++) acc[e] = bj;
        for (int k = 0; k < HDIM; k++) {
            float w = W2[k * HDIM + tid];
            const float4* v4 = reinterpret_cast<const float4*>(&s_m[k * STR]);
            #pragma unroll
            for (int q = 0; q < 8; q++) {
                float4 v = v4[q];
                acc[4 * q + 0] = fmaf(v.x, w, acc[4 * q + 0]);
                acc[4 * q + 1] = fmaf(v.y, w, acc[4 * q + 1]);
                acc[4 * q + 2] = fmaf(v.z, w, acc[4 * q + 2]);
                acc[4 * q + 3] = fmaf(v.w, w, acc[4 * q + 3]);
            }
        }
        #pragma unroll
        for (int e = 0; e < TILE; e++) {
            float mij = silu_f(acc[e]);
            s_mij[tid * STR + e] = mij;                       // aliases s_in (safe: past sync)
            atomicAdd(&g_msg[s_col[e] * HDIM + tid], mij);    // coalesced 128B RED
        }
    }
    __syncthreads();

    // ---- phase E: coord_weight = silu(m_ij @ C1 + cb1) @ C2 ----
    {
        float bj = cb1[tid];
        float c2 = C2[tid];
        #pragma unroll
        for (int e = 0; e < TILE; e++) acc[e] = bj;
        for (int k = 0; k < HDIM; k++) {
            float w = C1[k * HDIM + tid];
            const float4* v4 = reinterpret_cast<const float4*>(&s_mij[k * STR]);
            #pragma unroll
            for (int q = 0; q < 8; q++) {
                float4 v = v4[q];
                acc[4 * q + 0] = fmaf(v.x, w, acc[4 * q + 0]);
                acc[4 * q + 1] = fmaf(v.y, w, acc[4 * q + 1]);
                acc[4 * q + 2] = fmaf(v.z, w, acc[4 * q + 2]);
                acc[4 * q + 3] = fmaf(v.w, w, acc[4 * q + 3]);
            }
        }
        int lane = tid & 31, wrp = tid >> 5;
        #pragma unroll
        for (int e = 0; e < TILE; e++) {
            float p = silu_f(acc[e]) * c2;
            p += __shfl_xor_sync(0xFFFFFFFFu, p, 16);
            p += __shfl_xor_sync(0xFFFFFFFFu, p, 8);
            p += __shfl_xor_sync(0xFFFFFFFFu, p, 4);
            p += __shfl_xor_sync(0xFFFFFFFFu, p, 2);
            p += __shfl_xor_sync(0xFFFFFFFFu, p, 1);
            if (lane == 0) s_red[e * 8 + wrp] = p;
        }
        __syncthreads();
        if (tid < TILE) {
            float wsum = 0.0f;
            #pragma unroll
            for (int i = 0; i < 8; i++) wsum += s_red[tid * 8 + i];
            int c = s_col[tid];
            atomicAdd(&g_coord[c * 3 + 0], wsum * s_diff[tid * 3 + 0]);
            atomicAdd(&g_coord[c * 3 + 1], wsum * s_diff[tid * 3 + 1]);
            atomicAdd(&g_coord[c * 3 + 2], wsum * s_diff[tid * 3 + 2]);
        }
    }
}

// ---------------------------------------------------------------------------
// Node kernel: one block = 32 nodes. node MLP + residual + LayerNorm.
// ---------------------------------------------------------------------------
extern __shared__ float smem_n[];

__global__ __launch_bounds__(NTHR, 2)
void node_kernel(const float* __restrict__ h,
                 const float* __restrict__ NW1, const float* __restrict__ nb1,
                 const float* __restrict__ NW2, const float* __restrict__ nb2,
                 const float* __restrict__ lng, const float* __restrict__ lnb,
                 float* __restrict__ out_h)
{
    float* s_cat = smem_n;                  // 512 * 36 = 18432 (k-major [h | msg])
    float* s_u   = s_cat + 512 * STR;       // 256 * 36 =  9216
    float* s_r1  = s_u + 256 * STR;         // 256
    float* s_r2  = s_r1 + 256;              // 256
    float* s_mu  = s_r2 + 256;              // 32
    float* s_rs  = s_mu + 32;               // 32

    const int tid = threadIdx.x;
    const int n0  = blockIdx.x * TILE;

    for (int idx = tid; idx < TILE * 512; idx += NTHR) {
        int n = idx >> 9;
        int k = idx & 511;
        int node = n0 + n;
        float v = (k < HDIM) ? h[node * HDIM + k]
                             : g_msg[node * HDIM + (k - HDIM)];
        s_cat[k * STR + n] = v;
    }
    __syncthreads();

    float acc[TILE];

    // u = silu(h_cat @ NW1 + nb1)
    {
        float bj = nb1[tid];
        #pragma unroll
        for (int n = 0; n < TILE; n++) acc[n] = bj;
        for (int k = 0; k < 512; k++) {
            float w = NW1[k * HDIM + tid];
            const float4* v4 = reinterpret_cast<const float4*>(&s_cat[k * STR]);
            #pragma unroll
            for (int q = 0; q < 8; q++) {
                float4 v = v4[q];
                acc[4 * q + 0] = fmaf(v.x, w, acc[4 * q + 0]);
                acc[4 * q + 1] = fmaf(v.y, w, acc[4 * q + 1]);
                acc[4 * q + 2] = fmaf(v.z, w, acc[4 * q + 2]);
                acc[4 * q + 3] = fmaf(v.w, w, acc[4 * q + 3]);
            }
        }
        #pragma unroll
        for (int n = 0; n < TILE; n++) s_u[tid * STR + n] = silu_f(acc[n]);
    }
    __syncthreads();

    // y = u @ NW2 + nb2 + h ; LayerNorm
    {
        float bj = nb2[tid];
        #pragma unroll
        for (int n = 0; n < TILE; n++) acc[n] = bj;
        for (int k = 0; k < HDIM; k++) {
            float w = NW2[k * HDIM + tid];
            const float4* v4 = reinterpret_cast<const float4*>(&s_u[k * STR]);
            #pragma unroll
            for (int q = 0; q < 8; q++) {
                float4 v = v4[q];
                acc[4 * q + 0] = fmaf(v.x, w, acc[4 * q + 0]);
                acc[4 * q + 1] = fmaf(v.y, w, acc[4 * q + 1]);
                acc[4 * q + 2] = fmaf(v.z, w, acc[4 * q + 2]);
                acc[4 * q + 3] = fmaf(v.w, w, acc[4 * q + 3]);
            }
        }
        int lane = tid & 31, wrp = tid >> 5;
        #pragma unroll
        for (int n = 0; n < TILE; n++) {
            acc[n] += s_cat[tid * STR + n];        // residual: k=tid<256 row of s_cat is h
            float p1 = acc[n];
            float p2 = acc[n] * acc[n];
            #pragma unroll
            for (int o = 16; o; o >>= 1) {
                p1 += __shfl_xor_sync(0xFFFFFFFFu, p1, o);
                p2 += __shfl_xor_sync(0xFFFFFFFFu, p2, o);
            }
            if (lane == 0) { s_r1[n * 8 + wrp] = p1; s_r2[n * 8 + wrp] = p2; }
        }
        __syncthreads();
        if (tid < TILE) {
            float S1 = 0.0f, S2 = 0.0f;
            #pragma unroll
            for (int i = 0; i < 8; i++) { S1 += s_r1[tid * 8 + i]; S2 += s_r2[tid * 8 + i]; }
            float mu  = S1 * (1.0f / HDIM);
            float var = S2 * (1.0f / HDIM) - mu * mu;
            s_mu[tid] = mu;
            s_rs[tid] = rsqrtf(var + LN_EPS);
        }
        __syncthreads();
        float g = lng[tid], bb = lnb[tid];
        #pragma unroll
        for (int n = 0; n < TILE; n++) {
            out_h[(n0 + n) * HDIM + tid] = (acc[n] - s_mu[n]) * s_rs[n] * g + bb;
        }
    }
}

// ---------------------------------------------------------------------------
__global__ void xnew_kernel(const float* __restrict__ x, float* __restrict__ out_x) {
    int i = blockIdx.x * blockDim.x + threadIdx.x;
    if (i < NNODE * 3) out_x[i] = x[i] + g_coord[i];
}

// ---------------------------------------------------------------------------
extern "C" void kernel_launch(void* const* d_in, const int* in_sizes, int n_in,
                              void* d_out, int out_size)
{
    const float* h    = (const float*)d_in[0];
    const float* x    = (const float*)d_in[1];
    const void*  ei   = d_in[2];
    const float* e_w1 = (const float*)d_in[3];
    const float* e_b1 = (const float*)d_in[4];
    const float* e_w2 = (const float*)d_in[5];
    const float* e_b2 = (const float*)d_in[6];
    const float* c_w1 = (const float*)d_in[7];
    const float* c_b1 = (const float*)d_in[8];
    const float* c_w2 = (const float*)d_in[9];
    const float* n_w1 = (const float*)d_in[10];
    const float* n_b1 = (const float*)d_in[11];
    const float* n_w2 = (const float*)d_in[12];
    const float* n_b2 = (const float*)d_in[13];
    const float* ln_g = (const float*)d_in[14];
    const float* ln_b = (const float*)d_in[15];
    float* out = (float*)d_out;

    const int edge_smem = (513 * STR + 256 * STR + 96 + 256 + 64) * 4;
    const int node_smem = (512 * STR + 256 * STR + 256 + 256 + 64) * 4;

    cudaFuncSetAttribute(edge_kernel, cudaFuncAttributeMaxDynamicSharedMemorySize, edge_smem);
    cudaFuncSetAttribute(node_kernel, cudaFuncAttributeMaxDynamicSharedMemorySize, node_smem);

    detect_kernel<<<1, 32>>>((const unsigned*)ei);
    zero_kernel<<<512, NTHR>>>();
    edge_kernel<<<NEDGE / TILE, NTHR, edge_smem>>>(h, x, ei,
                                                   e_w1, e_b1, e_w2, e_b2,
                                                   c_w1, c_b1, c_w2);
    node_kernel<<<NNODE / TILE, NTHR, node_smem>>>(h, n_w1, n_b1, n_w2, n_b2,
                                                   ln_g, ln_b, out);
    xnew_kernel<<<(NNODE * 3 + NTHR - 1) / NTHR, NTHR>>>(x, out + NNODE * HDIM);
}

// round 3
// speedup vs baseline: 1.1945x; 1.1945x over previous
#include <cuda_runtime.h>

// ---------------------------------------------------------------------------
// EGNN layer: N=20000 nodes, E=320000 edges, H=256.
// Round 3: fma.rn.f32x2 packed FMAs (halve FMA issue count) + chunked K
// staging (smem 112KB -> 57KB) + __launch_bounds__(256,3) -> 3 blocks/SM.
// ---------------------------------------------------------------------------

#define HDIM    256
#define NNODE   20000
#define NEDGE   320000
#define TILE    32
#define NTHR    256
#define STR     36          // smem row stride in floats (144B, 16B aligned)
#define CHUNK   128         // K-rows staged per chunk
#define LN_EPS  1e-5f

// scratch (device globals: allocation-free per harness rules)
__device__ float g_msg[NNODE * HDIM];     // 20.5 MB
__device__ float g_coord[NNODE * 3];
__device__ int   g_is64;                  // 1 if edge_index is int64

__device__ __forceinline__ float silu_f(float v) {
    return v / (1.0f + __expf(-v));
}

__device__ __forceinline__ unsigned long long pack2(float a, float b) {
    unsigned long long r;
    asm("mov.b64 %0, {%1, %2};" : "=l"(r) : "f"(a), "f"(b));
    return r;
}
__device__ __forceinline__ float2 unpack2(unsigned long long v) {
    float2 r;
    asm("mov.b64 {%0, %1}, %2;" : "=f"(r.x), "=f"(r.y) : "l"(v));
    return r;
}
#define FFMA2(acc, v, w) \
    asm("fma.rn.f32x2 %0, %1, %2, %0;" : "+l"(acc) : "l"(v), "l"(w))

// ---------------------------------------------------------------------------
// Detect edge_index dtype (JAX x64 ambiguity). Reads first 8KB only.
// ---------------------------------------------------------------------------
__global__ void detect_kernel(const unsigned* __restrict__ w) {
    unsigned acc = 0;
    for (int i = threadIdx.x; i < 1024; i += 32) acc |= w[2 * i + 1];
    #pragma unroll
    for (int o = 16; o; o >>= 1) acc |= __shfl_xor_sync(0xFFFFFFFFu, acc, o);
    if (threadIdx.x == 0) g_is64 = (acc == 0) ? 1 : 0;
}

// ---------------------------------------------------------------------------
__global__ void zero_kernel() {
    int i = blockIdx.x * blockDim.x + threadIdx.x;
    int stride = gridDim.x * blockDim.x;
    for (int idx = i; idx < NNODE * HDIM; idx += stride) g_msg[idx] = 0.0f;
    for (int idx = i; idx < NNODE * 3;    idx += stride) g_coord[idx] = 0.0f;
}

// ---------------------------------------------------------------------------
// Edge kernel: one block = 32 edges, thread tid owns output feature j = tid.
// Accumulators: 16 x f32x2 pairs (32 edges). K staged in 128-row chunks.
// ---------------------------------------------------------------------------
extern __shared__ float smem_e[];

__global__ __launch_bounds__(NTHR, 3)
void edge_kernel(const float* __restrict__ h, const float* __restrict__ x,
                 const void* __restrict__ ei_raw,
                 const float* __restrict__ W1, const float* __restrict__ b1,
                 const float* __restrict__ W2, const float* __restrict__ b2,
                 const float* __restrict__ C1, const float* __restrict__ cb1,
                 const float* __restrict__ C2)
{
    // smem layout (floats)
    float* s_buf  = smem_e;                 // CHUNK * 36 = 4608  (staging)
    float* s_m    = s_buf + CHUNK * STR;    // 256 * 36   = 9216  (m / m_ij)
    float* s_dist = s_m + 256 * STR;        // 32 (dist_sq row, 16B aligned)
    float* s_diff = s_dist + 32;            // 96
    float* s_red  = s_diff + 96;            // 256
    int*   s_row  = (int*)(s_red + 256);    // 32
    int*   s_col  = s_row + 32;             // 32

    const int tid = threadIdx.x;
    const int e0  = blockIdx.x * TILE;

    if (tid < TILE) {
        int e = e0 + tid;
        int r, c;
        if (g_is64) {
            const long long* p = (const long long*)ei_raw;
            r = (int)p[e];
            c = (int)p[NEDGE + e];
        } else {
            const int* p = (const int*)ei_raw;
            r = p[e];
            c = p[NEDGE + e];
        }
        s_row[tid] = r;
        s_col[tid] = c;
        float dx = x[r * 3 + 0] - x[c * 3 + 0];
        float dy = x[r * 3 + 1] - x[c * 3 + 1];
        float dz = x[r * 3 + 2] - x[c * 3 + 2];
        s_diff[tid * 3 + 0] = dx;
        s_diff[tid * 3 + 1] = dy;
        s_diff[tid * 3 + 2] = dz;
        s_dist[tid] = dx * dx + dy * dy + dz * dz;
    }

    unsigned long long acc[16];

    // ---- phase B: m = silu(edge_input @ W1 + b1), K = 513 ----
    {
        float bj = b1[tid];
        unsigned long long bp = pack2(bj, bj);
        #pragma unroll
        for (int i = 0; i < 16; i++) acc[i] = bp;

        for (int c0 = 0; c0 < 512; c0 += CHUNK) {
            __syncthreads();   // s_buf free (also covers s_row/s_col on 1st pass)
            for (int idx = tid; idx < TILE * CHUNK; idx += NTHR) {
                int e = idx >> 7;           // / CHUNK
                int k = idx & (CHUNK - 1);
                int kk = c0 + k;
                int node = (kk < HDIM) ? s_row[e] : s_col[e];
                s_buf[k * STR + e] = h[node * HDIM + (kk & (HDIM - 1))];
            }
            __syncthreads();
            for (int k = 0; k < CHUNK; k++) {
                float w = W1[(c0 + k) * HDIM + tid];
                unsigned long long wp = pack2(w, w);
                const ulonglong2* v = reinterpret_cast<const ulonglong2*>(&s_buf[k * STR]);
                #pragma unroll
                for (int q = 0; q < 8; q++) {
                    ulonglong2 p = v[q];
                    FFMA2(acc[2 * q + 0], p.x, wp);
                    FFMA2(acc[2 * q + 1], p.y, wp);
                }
            }
        }
        // dist_sq term (k = 512)
        {
            float wd = W1[512 * HDIM + tid];
            unsigned long long wp = pack2(wd, wd);
            const ulonglong2* v = reinterpret_cast<const ulonglong2*>(s_dist);
            #pragma unroll
            for (int q = 0; q < 8; q++) {
                ulonglong2 p = v[q];
                FFMA2(acc[2 * q + 0], p.x, wp);
                FFMA2(acc[2 * q + 1], p.y, wp);
            }
        }
        #pragma unroll
        for (int i = 0; i < 16; i++) {
            float2 a = unpack2(acc[i]);
            s_m[tid * STR + 2 * i + 0] = silu_f(a.x);
            s_m[tid * STR + 2 * i + 1] = silu_f(a.y);
        }
    }
    __syncthreads();

    // ---- phase D: m_ij = silu(m @ W2 + b2); scatter to g_msg ----
    {
        float bj = b2[tid];
        unsigned long long bp = pack2(bj, bj);
        #pragma unroll
        for (int i = 0; i < 16; i++) acc[i] = bp;
        for (int k = 0; k < HDIM; k++) {
            float w = W2[k * HDIM + tid];
            unsigned long long wp = pack2(w, w);
            const ulonglong2* v = reinterpret_cast<const ulonglong2*>(&s_m[k * STR]);
            #pragma unroll
            for (int q = 0; q < 8; q++) {
                ulonglong2 p = v[q];
                FFMA2(acc[2 * q + 0], p.x, wp);
                FFMA2(acc[2 * q + 1], p.y, wp);
            }
        }
        __syncthreads();   // everyone done reading m before overwrite
        #pragma unroll
        for (int i = 0; i < 16; i++) {
            float2 a = unpack2(acc[i]);
            float m0 = silu_f(a.x);
            float m1 = silu_f(a.y);
            s_m[tid * STR + 2 * i + 0] = m0;           // m_ij overwrites m
            s_m[tid * STR + 2 * i + 1] = m1;
            atomicAdd(&g_msg[s_col[2 * i + 0] * HDIM + tid], m0);
            atomicAdd(&g_msg[s_col[2 * i + 1] * HDIM + tid], m1);
        }
    }
    __syncthreads();

    // ---- phase E: coord_weight = silu(m_ij @ C1 + cb1) @ C2 ----
    {
        float bj = cb1[tid];
        float c2 = C2[tid];
        unsigned long long bp = pack2(bj, bj);
        #pragma unroll
        for (int i = 0; i < 16; i++) acc[i] = bp;
        for (int k = 0; k < HDIM; k++) {
            float w = C1[k * HDIM + tid];
            unsigned long long wp = pack2(w, w);
            const ulonglong2* v = reinterpret_cast<const ulonglong2*>(&s_m[k * STR]);
            #pragma unroll
            for (int q = 0; q < 8; q++) {
                ulonglong2 p = v[q];
                FFMA2(acc[2 * q + 0], p.x, wp);
                FFMA2(acc[2 * q + 1], p.y, wp);
            }
        }
        int lane = tid & 31, wrp = tid >> 5;
        #pragma unroll
        for (int i = 0; i < 16; i++) {
            float2 a = unpack2(acc[i]);
            #pragma unroll
            for (int half = 0; half < 2; half++) {
                float p = silu_f(half ? a.y : a.x) * c2;
                p += __shfl_xor_sync(0xFFFFFFFFu, p, 16);
                p += __shfl_xor_sync(0xFFFFFFFFu, p, 8);
                p += __shfl_xor_sync(0xFFFFFFFFu, p, 4);
                p += __shfl_xor_sync(0xFFFFFFFFu, p, 2);
                p += __shfl_xor_sync(0xFFFFFFFFu, p, 1);
                if (lane == 0) s_red[(2 * i + half) * 8 + wrp] = p;
            }
        }
        __syncthreads();
        if (tid < TILE) {
            float wsum = 0.0f;
            #pragma unroll
            for (int i = 0; i < 8; i++) wsum += s_red[tid * 8 + i];
            int c = s_col[tid];
            atomicAdd(&g_coord[c * 3 + 0], wsum * s_diff[tid * 3 + 0]);
            atomicAdd(&g_coord[c * 3 + 1], wsum * s_diff[tid * 3 + 1]);
            atomicAdd(&g_coord[c * 3 + 2], wsum * s_diff[tid * 3 + 2]);
        }
    }
}

// ---------------------------------------------------------------------------
// Node kernel: one block = 32 nodes. node MLP + residual + LayerNorm.
// ---------------------------------------------------------------------------
extern __shared__ float smem_n[];

__global__ __launch_bounds__(NTHR, 3)
void node_kernel(const float* __restrict__ h,
                 const float* __restrict__ NW1, const float* __restrict__ nb1,
                 const float* __restrict__ NW2, const float* __restrict__ nb2,
                 const float* __restrict__ lng, const float* __restrict__ lnb,
                 float* __restrict__ out_h)
{
    float* s_buf = smem_n;                  // CHUNK * 36 = 4608 (staging)
    float* s_u   = s_buf + CHUNK * STR;     // 256 * 36   = 9216
    float* s_r1  = s_u + 256 * STR;         // 256
    float* s_r2  = s_r1 + 256;              // 256
    float* s_mu  = s_r2 + 256;              // 32
    float* s_rs  = s_mu + 32;               // 32

    const int tid = threadIdx.x;
    const int n0  = blockIdx.x * TILE;

    unsigned long long acc[16];

    // u = silu(h_cat @ NW1 + nb1), K = 512 chunked
    {
        float bj = nb1[tid];
        unsigned long long bp = pack2(bj, bj);
        #pragma unroll
        for (int i = 0; i < 16; i++) acc[i] = bp;

        for (int c0 = 0; c0 < 512; c0 += CHUNK) {
            __syncthreads();
            for (int idx = tid; idx < TILE * CHUNK; idx += NTHR) {
                int n = idx >> 7;
                int k = idx & (CHUNK - 1);
                int kk = c0 + k;
                int node = n0 + n;
                float v = (kk < HDIM) ? h[node * HDIM + kk]
                                      : g_msg[node * HDIM + (kk - HDIM)];
                s_buf[k * STR + n] = v;
            }
            __syncthreads();
            for (int k = 0; k < CHUNK; k++) {
                float w = NW1[(c0 + k) * HDIM + tid];
                unsigned long long wp = pack2(w, w);
                const ulonglong2* v = reinterpret_cast<const ulonglong2*>(&s_buf[k * STR]);
                #pragma unroll
                for (int q = 0; q < 8; q++) {
                    ulonglong2 p = v[q];
                    FFMA2(acc[2 * q + 0], p.x, wp);
                    FFMA2(acc[2 * q + 1], p.y, wp);
                }
            }
        }
        #pragma unroll
        for (int i = 0; i < 16; i++) {
            float2 a = unpack2(acc[i]);
            s_u[tid * STR + 2 * i + 0] = silu_f(a.x);
            s_u[tid * STR + 2 * i + 1] = silu_f(a.y);
        }
    }
    __syncthreads();

    // y = u @ NW2 + nb2 + h ; LayerNorm
    {
        float bj = nb2[tid];
        unsigned long long bp = pack2(bj, bj);
        #pragma unroll
        for (int i = 0; i < 16; i++) acc[i] = bp;
        for (int k = 0; k < HDIM; k++) {
            float w = NW2[k * HDIM + tid];
            unsigned long long wp = pack2(w, w);
            const ulonglong2* v = reinterpret_cast<const ulonglong2*>(&s_u[k * STR]);
            #pragma unroll
            for (int q = 0; q < 8; q++) {
                ulonglong2 p = v[q];
                FFMA2(acc[2 * q + 0], p.x, wp);
                FFMA2(acc[2 * q + 1], p.y, wp);
            }
        }
        int lane = tid & 31, wrp = tid >> 5;
        float y[TILE];
        #pragma unroll
        for (int i = 0; i < 16; i++) {
            float2 a = unpack2(acc[i]);
            // residual: h[(n0+n)*H + tid], coalesced per n (L1/L2 hit)
            y[2 * i + 0] = a.x + h[(n0 + 2 * i + 0) * HDIM + tid];
            y[2 * i + 1] = a.y + h[(n0 + 2 * i + 1) * HDIM + tid];
        }
        #pragma unroll
        for (int n = 0; n < TILE; n++) {
            float p1 = y[n];
            float p2 = y[n] * y[n];
            #pragma unroll
            for (int o = 16; o; o >>= 1) {
                p1 += __shfl_xor_sync(0xFFFFFFFFu, p1, o);
                p2 += __shfl_xor_sync(0xFFFFFFFFu, p2, o);
            }
            if (lane == 0) { s_r1[n * 8 + wrp] = p1; s_r2[n * 8 + wrp] = p2; }
        }
        __syncthreads();
        if (tid < TILE) {
            float S1 = 0.0f, S2 = 0.0f;
            #pragma unroll
            for (int i = 0; i < 8; i++) { S1 += s_r1[tid * 8 + i]; S2 += s_r2[tid * 8 + i]; }
            float mu  = S1 * (1.0f / HDIM);
            float var = S2 * (1.0f / HDIM) - mu * mu;
            s_mu[tid] = mu;
            s_rs[tid] = rsqrtf(var + LN_EPS);
        }
        __syncthreads();
        float g = lng[tid], bb = lnb[tid];
        #pragma unroll
        for (int n = 0; n < TILE; n++) {
            out_h[(n0 + n) * HDIM + tid] = (y[n] - s_mu[n]) * s_rs[n] * g + bb;
        }
    }
}

// ---------------------------------------------------------------------------
__global__ void xnew_kernel(const float* __restrict__ x, float* __restrict__ out_x) {
    int i = blockIdx.x * blockDim.x + threadIdx.x;
    if (i < NNODE * 3) out_x[i] = x[i] + g_coord[i];
}

// ---------------------------------------------------------------------------
extern "C" void kernel_launch(void* const* d_in, const int* in_sizes, int n_in,
                              void* d_out, int out_size)
{
    const float* h    = (const float*)d_in[0];
    const float* x    = (const float*)d_in[1];
    const void*  ei   = d_in[2];
    const float* e_w1 = (const float*)d_in[3];
    const float* e_b1 = (const float*)d_in[4];
    const float* e_w2 = (const float*)d_in[5];
    const float* e_b2 = (const float*)d_in[6];
    const float* c_w1 = (const float*)d_in[7];
    const float* c_b1 = (const float*)d_in[8];
    const float* c_w2 = (const float*)d_in[9];
    const float* n_w1 = (const float*)d_in[10];
    const float* n_b1 = (const float*)d_in[11];
    const float* n_w2 = (const float*)d_in[12];
    const float* n_b2 = (const float*)d_in[13];
    const float* ln_g = (const float*)d_in[14];
    const float* ln_b = (const float*)d_in[15];
    float* out = (float*)d_out;

    const int edge_smem = (CHUNK * STR + 256 * STR + 32 + 96 + 256) * 4 + 256;
    const int node_smem = (CHUNK * STR + 256 * STR + 256 + 256 + 32 + 32) * 4;

    cudaFuncSetAttribute(edge_kernel, cudaFuncAttributeMaxDynamicSharedMemorySize, edge_smem);
    cudaFuncSetAttribute(node_kernel, cudaFuncAttributeMaxDynamicSharedMemorySize, node_smem);

    detect_kernel<<<1, 32>>>((const unsigned*)ei);
    zero_kernel<<<512, NTHR>>>();
    edge_kernel<<<NEDGE / TILE, NTHR, edge_smem>>>(h, x, ei,
                                                   e_w1, e_b1, e_w2, e_b2,
                                                   c_w1, c_b1, c_w2);
    node_kernel<<<NNODE / TILE, NTHR, node_smem>>>(h, n_w1, n_b1, n_w2, n_b2,
                                                   ln_g, ln_b, out);
    xnew_kernel<<<(NNODE * 3 + NTHR - 1) / NTHR, NTHR>>>(x, out + NNODE * HDIM);
}

// round 4
// speedup vs baseline: 2.1011x; 1.7590x over previous
#include <cuda_runtime.h>

// ---------------------------------------------------------------------------
// EGNN layer: N=20000 nodes, E=320000 edges, H=256.
// Round 4: algebraic split of edge-MLP layer 1:
//   edge_input @ W1 = P[row] + Q[col] + dist_sq * W1[512]   (P,Q per-node)
// removes 84 of 168 GFLOP and half the edge-kernel LDS traffic.
// ---------------------------------------------------------------------------

#define HDIM    256
#define NNODE   20000
#define NEDGE   320000
#define TILE    32
#define NTHR    256
#define STR     36          // smem row stride in floats (144B, 16B aligned)
#define CHUNK   128         // K-rows staged per chunk
#define LN_EPS  1e-5f

// scratch (device globals: allocation-free per harness rules)
__device__ float g_msg[NNODE * HDIM];     // 20.5 MB
__device__ float g_P[NNODE * HDIM];       // h @ W1[0:256]
__device__ float g_Q[NNODE * HDIM];       // h @ W1[256:512]
__device__ float g_coord[NNODE * 3];
__device__ int   g_is64;                  // 1 if edge_index is int64

__device__ __forceinline__ float silu_f(float v) {
    return v / (1.0f + __expf(-v));
}

__device__ __forceinline__ unsigned long long pack2(float a, float b) {
    unsigned long long r;
    asm("mov.b64 %0, {%1, %2};" : "=l"(r) : "f"(a), "f"(b));
    return r;
}
__device__ __forceinline__ float2 unpack2(unsigned long long v) {
    float2 r;
    asm("mov.b64 {%0, %1}, %2;" : "=f"(r.x), "=f"(r.y) : "l"(v));
    return r;
}
#define FFMA2(acc, v, w) \
    asm("fma.rn.f32x2 %0, %1, %2, %0;" : "+l"(acc) : "l"(v), "l"(w))

// ---------------------------------------------------------------------------
// Detect edge_index dtype (JAX x64 ambiguity). Reads first 8KB only.
// ---------------------------------------------------------------------------
__global__ void detect_kernel(const unsigned* __restrict__ w) {
    unsigned acc = 0;
    for (int i = threadIdx.x; i < 1024; i += 32) acc |= w[2 * i + 1];
    #pragma unroll
    for (int o = 16; o; o >>= 1) acc |= __shfl_xor_sync(0xFFFFFFFFu, acc, o);
    if (threadIdx.x == 0) g_is64 = (acc == 0) ? 1 : 0;
}

// ---------------------------------------------------------------------------
__global__ void zero_kernel() {
    int i = blockIdx.x * blockDim.x + threadIdx.x;
    int stride = gridDim.x * blockDim.x;
    for (int idx = i; idx < NNODE * HDIM; idx += stride) g_msg[idx] = 0.0f;
    for (int idx = i; idx < NNODE * 3;    idx += stride) g_coord[idx] = 0.0f;
}

// ---------------------------------------------------------------------------
// Precompute kernel: P = h @ W1[0:256], Q = h @ W1[256:512].
// blockIdx.y selects side. One block = 32 nodes, thread = feature.
// ---------------------------------------------------------------------------
extern __shared__ float smem_p[];

__global__ __launch_bounds__(NTHR, 3)
void precomp_kernel(const float* __restrict__ h, const float* __restrict__ W1)
{
    float* s_buf = smem_p;                  // CHUNK * 36 = 4608

    const int tid  = threadIdx.x;
    const int n0   = blockIdx.x * TILE;
    const int side = blockIdx.y;            // 0 -> P, 1 -> Q
    const float* W = W1 + side * HDIM * HDIM;
    float* out = side ? g_Q : g_P;

    unsigned long long acc[16];
    #pragma unroll
    for (int i = 0; i < 16; i++) acc[i] = 0ULL;

    for (int c0 = 0; c0 < HDIM; c0 += CHUNK) {
        __syncthreads();
        for (int idx = tid; idx < TILE * CHUNK; idx += NTHR) {
            int n = idx >> 7;
            int k = idx & (CHUNK - 1);
            s_buf[k * STR + n] = h[(n0 + n) * HDIM + c0 + k];
        }
        __syncthreads();
        for (int k = 0; k < CHUNK; k++) {
            float w = W[(c0 + k) * HDIM + tid];
            unsigned long long wp = pack2(w, w);
            const ulonglong2* v = reinterpret_cast<const ulonglong2*>(&s_buf[k * STR]);
            #pragma unroll
            for (int q = 0; q < 8; q++) {
                ulonglong2 p = v[q];
                FFMA2(acc[2 * q + 0], p.x, wp);
                FFMA2(acc[2 * q + 1], p.y, wp);
            }
        }
    }
    #pragma unroll
    for (int i = 0; i < 16; i++) {
        float2 a = unpack2(acc[i]);
        out[(n0 + 2 * i + 0) * HDIM + tid] = a.x;
        out[(n0 + 2 * i + 1) * HDIM + tid] = a.y;
    }
}

// ---------------------------------------------------------------------------
// Edge kernel: one block = 32 edges, thread tid owns output feature j = tid.
// Phase B is now a gather: m = silu(P[row] + Q[col] + dist*w1d + b1).
// ---------------------------------------------------------------------------
extern __shared__ float smem_e[];

__global__ __launch_bounds__(NTHR, 3)
void edge_kernel(const float* __restrict__ x,
                 const void* __restrict__ ei_raw,
                 const float* __restrict__ W1, const float* __restrict__ b1,
                 const float* __restrict__ W2, const float* __restrict__ b2,
                 const float* __restrict__ C1, const float* __restrict__ cb1,
                 const float* __restrict__ C2)
{
    // smem layout (floats)
    float* s_m    = smem_e;                 // 256 * 36 = 9216 (m / m_ij)
    float* s_dist = s_m + 256 * STR;        // 32
    float* s_diff = s_dist + 32;            // 96
    float* s_red  = s_diff + 96;            // 256
    int*   s_row  = (int*)(s_red + 256);    // 32
    int*   s_col  = s_row + 32;             // 32

    const int tid = threadIdx.x;
    const int e0  = blockIdx.x * TILE;

    if (tid < TILE) {
        int e = e0 + tid;
        int r, c;
        if (g_is64) {
            const long long* p = (const long long*)ei_raw;
            r = (int)p[e];
            c = (int)p[NEDGE + e];
        } else {
            const int* p = (const int*)ei_raw;
            r = p[e];
            c = p[NEDGE + e];
        }
        s_row[tid] = r;
        s_col[tid] = c;
        float dx = x[r * 3 + 0] - x[c * 3 + 0];
        float dy = x[r * 3 + 1] - x[c * 3 + 1];
        float dz = x[r * 3 + 2] - x[c * 3 + 2];
        s_diff[tid * 3 + 0] = dx;
        s_diff[tid * 3 + 1] = dy;
        s_diff[tid * 3 + 2] = dz;
        s_dist[tid] = dx * dx + dy * dy + dz * dz;
    }
    __syncthreads();

    // ---- phase B (gather): m[j][e] = silu(P[row]+Q[col]+dist*w1d+b1) ----
    {
        float w1d = W1[512 * HDIM + tid];
        float b1j = b1[tid];
        #pragma unroll 4
        for (int e = 0; e < TILE; e++) {
            int r = s_row[e], c = s_col[e];
            float v = g_P[r * HDIM + tid] + g_Q[c * HDIM + tid] + b1j;
            v = fmaf(s_dist[e], w1d, v);
            s_m[tid * STR + e] = silu_f(v);
        }
    }
    __syncthreads();

    unsigned long long acc[16];

    // ---- phase D: m_ij = silu(m @ W2 + b2); scatter to g_msg ----
    {
        float bj = b2[tid];
        unsigned long long bp = pack2(bj, bj);
        #pragma unroll
        for (int i = 0; i < 16; i++) acc[i] = bp;
        for (int k = 0; k < HDIM; k++) {
            float w = W2[k * HDIM + tid];
            unsigned long long wp = pack2(w, w);
            const ulonglong2* v = reinterpret_cast<const ulonglong2*>(&s_m[k * STR]);
            #pragma unroll
            for (int q = 0; q < 8; q++) {
                ulonglong2 p = v[q];
                FFMA2(acc[2 * q + 0], p.x, wp);
                FFMA2(acc[2 * q + 1], p.y, wp);
            }
        }
        __syncthreads();   // everyone done reading m before overwrite
        #pragma unroll
        for (int i = 0; i < 16; i++) {
            float2 a = unpack2(acc[i]);
            float m0 = silu_f(a.x);
            float m1 = silu_f(a.y);
            s_m[tid * STR + 2 * i + 0] = m0;           // m_ij overwrites m
            s_m[tid * STR + 2 * i + 1] = m1;
            atomicAdd(&g_msg[s_col[2 * i + 0] * HDIM + tid], m0);
            atomicAdd(&g_msg[s_col[2 * i + 1] * HDIM + tid], m1);
        }
    }
    __syncthreads();

    // ---- phase E: coord_weight = silu(m_ij @ C1 + cb1) @ C2 ----
    {
        float bj = cb1[tid];
        float c2 = C2[tid];
        unsigned long long bp = pack2(bj, bj);
        #pragma unroll
        for (int i = 0; i < 16; i++) acc[i] = bp;
        for (int k = 0; k < HDIM; k++) {
            float w = C1[k * HDIM + tid];
            unsigned long long wp = pack2(w, w);
            const ulonglong2* v = reinterpret_cast<const ulonglong2*>(&s_m[k * STR]);
            #pragma unroll
            for (int q = 0; q < 8; q++) {
                ulonglong2 p = v[q];
                FFMA2(acc[2 * q + 0], p.x, wp);
                FFMA2(acc[2 * q + 1], p.y, wp);
            }
        }
        int lane = tid & 31, wrp = tid >> 5;
        #pragma unroll
        for (int i = 0; i < 16; i++) {
            float2 a = unpack2(acc[i]);
            #pragma unroll
            for (int half = 0; half < 2; half++) {
                float p = silu_f(half ? a.y : a.x) * c2;
                p += __shfl_xor_sync(0xFFFFFFFFu, p, 16);
                p += __shfl_xor_sync(0xFFFFFFFFu, p, 8);
                p += __shfl_xor_sync(0xFFFFFFFFu, p, 4);
                p += __shfl_xor_sync(0xFFFFFFFFu, p, 2);
                p += __shfl_xor_sync(0xFFFFFFFFu, p, 1);
                if (lane == 0) s_red[(2 * i + half) * 8 + wrp] = p;
            }
        }
        __syncthreads();
        if (tid < TILE) {
            float wsum = 0.0f;
            #pragma unroll
            for (int i = 0; i < 8; i++) wsum += s_red[tid * 8 + i];
            int c = s_col[tid];
            atomicAdd(&g_coord[c * 3 + 0], wsum * s_diff[tid * 3 + 0]);
            atomicAdd(&g_coord[c * 3 + 1], wsum * s_diff[tid * 3 + 1]);
            atomicAdd(&g_coord[c * 3 + 2], wsum * s_diff[tid * 3 + 2]);
        }
    }
}

// ---------------------------------------------------------------------------
// Node kernel: one block = 32 nodes. node MLP + residual + LayerNorm.
// ---------------------------------------------------------------------------
extern __shared__ float smem_n[];

__global__ __launch_bounds__(NTHR, 3)
void node_kernel(const float* __restrict__ h,
                 const float* __restrict__ NW1, const float* __restrict__ nb1,
                 const float* __restrict__ NW2, const float* __restrict__ nb2,
                 const float* __restrict__ lng, const float* __restrict__ lnb,
                 float* __restrict__ out_h)
{
    float* s_buf = smem_n;                  // CHUNK * 36 = 4608 (staging)
    float* s_u   = s_buf + CHUNK * STR;     // 256 * 36   = 9216
    float* s_r1  = s_u + 256 * STR;         // 256
    float* s_r2  = s_r1 + 256;              // 256
    float* s_mu  = s_r2 + 256;              // 32
    float* s_rs  = s_mu + 32;               // 32

    const int tid = threadIdx.x;
    const int n0  = blockIdx.x * TILE;

    unsigned long long acc[16];

    // u = silu(h_cat @ NW1 + nb1), K = 512 chunked
    {
        float bj = nb1[tid];
        unsigned long long bp = pack2(bj, bj);
        #pragma unroll
        for (int i = 0; i < 16; i++) acc[i] = bp;

        for (int c0 = 0; c0 < 512; c0 += CHUNK) {
            __syncthreads();
            for (int idx = tid; idx < TILE * CHUNK; idx += NTHR) {
                int n = idx >> 7;
                int k = idx & (CHUNK - 1);
                int kk = c0 + k;
                int node = n0 + n;
                float v = (kk < HDIM) ? h[node * HDIM + kk]
                                      : g_msg[node * HDIM + (kk - HDIM)];
                s_buf[k * STR + n] = v;
            }
            __syncthreads();
            for (int k = 0; k < CHUNK; k++) {
                float w = NW1[(c0 + k) * HDIM + tid];
                unsigned long long wp = pack2(w, w);
                const ulonglong2* v = reinterpret_cast<const ulonglong2*>(&s_buf[k * STR]);
                #pragma unroll
                for (int q = 0; q < 8; q++) {
                    ulonglong2 p = v[q];
                    FFMA2(acc[2 * q + 0], p.x, wp);
                    FFMA2(acc[2 * q + 1], p.y, wp);
                }
            }
        }
        #pragma unroll
        for (int i = 0; i < 16; i++) {
            float2 a = unpack2(acc[i]);
            s_u[tid * STR + 2 * i + 0] = silu_f(a.x);
            s_u[tid * STR + 2 * i + 1] = silu_f(a.y);
        }
    }
    __syncthreads();

    // y = u @ NW2 + nb2 + h ; LayerNorm
    {
        float bj = nb2[tid];
        unsigned long long bp = pack2(bj, bj);
        #pragma unroll
        for (int i = 0; i < 16; i++) acc[i] = bp;
        for (int k = 0; k < HDIM; k++) {
            float w = NW2[k * HDIM + tid];
            unsigned long long wp = pack2(w, w);
            const ulonglong2* v = reinterpret_cast<const ulonglong2*>(&s_u[k * STR]);
            #pragma unroll
            for (int q = 0; q < 8; q++) {
                ulonglong2 p = v[q];
                FFMA2(acc[2 * q + 0], p.x, wp);
                FFMA2(acc[2 * q + 1], p.y, wp);
            }
        }
        int lane = tid & 31, wrp = tid >> 5;
        float y[TILE];
        #pragma unroll
        for (int i = 0; i < 16; i++) {
            float2 a = unpack2(acc[i]);
            y[2 * i + 0] = a.x + h[(n0 + 2 * i + 0) * HDIM + tid];
            y[2 * i + 1] = a.y + h[(n0 + 2 * i + 1) * HDIM + tid];
        }
        #pragma unroll
        for (int n = 0; n < TILE; n++) {
            float p1 = y[n];
            float p2 = y[n] * y[n];
            #pragma unroll
            for (int o = 16; o; o >>= 1) {
                p1 += __shfl_xor_sync(0xFFFFFFFFu, p1, o);
                p2 += __shfl_xor_sync(0xFFFFFFFFu, p2, o);
            }
            if (lane == 0) { s_r1[n * 8 + wrp] = p1; s_r2[n * 8 + wrp] = p2; }
        }
        __syncthreads();
        if (tid < TILE) {
            float S1 = 0.0f, S2 = 0.0f;
            #pragma unroll
            for (int i = 0; i < 8; i++) { S1 += s_r1[tid * 8 + i]; S2 += s_r2[tid * 8 + i]; }
            float mu  = S1 * (1.0f / HDIM);
            float var = S2 * (1.0f / HDIM) - mu * mu;
            s_mu[tid] = mu;
            s_rs[tid] = rsqrtf(var + LN_EPS);
        }
        __syncthreads();
        float g = lng[tid], bb = lnb[tid];
        #pragma unroll
        for (int n = 0; n < TILE; n++) {
            out_h[(n0 + n) * HDIM + tid] = (y[n] - s_mu[n]) * s_rs[n] * g + bb;
        }
    }
}

// ---------------------------------------------------------------------------
__global__ void xnew_kernel(const float* __restrict__ x, float* __restrict__ out_x) {
    int i = blockIdx.x * blockDim.x + threadIdx.x;
    if (i < NNODE * 3) out_x[i] = x[i] + g_coord[i];
}

// ---------------------------------------------------------------------------
extern "C" void kernel_launch(void* const* d_in, const int* in_sizes, int n_in,
                              void* d_out, int out_size)
{
    const float* h    = (const float*)d_in[0];
    const float* x    = (const float*)d_in[1];
    const void*  ei   = d_in[2];
    const float* e_w1 = (const float*)d_in[3];
    const float* e_b1 = (const float*)d_in[4];
    const float* e_w2 = (const float*)d_in[5];
    const float* e_b2 = (const float*)d_in[6];
    const float* c_w1 = (const float*)d_in[7];
    const float* c_b1 = (const float*)d_in[8];
    const float* c_w2 = (const float*)d_in[9];
    const float* n_w1 = (const float*)d_in[10];
    const float* n_b1 = (const float*)d_in[11];
    const float* n_w2 = (const float*)d_in[12];
    const float* n_b2 = (const float*)d_in[13];
    const float* ln_g = (const float*)d_in[14];
    const float* ln_b = (const float*)d_in[15];
    float* out = (float*)d_out;

    const int prec_smem = (CHUNK * STR) * 4;
    const int edge_smem = (256 * STR + 32 + 96 + 256 + 64) * 4;
    const int node_smem = (CHUNK * STR + 256 * STR + 256 + 256 + 32 + 32) * 4;

    cudaFuncSetAttribute(precomp_kernel, cudaFuncAttributeMaxDynamicSharedMemorySize, prec_smem);
    cudaFuncSetAttribute(edge_kernel, cudaFuncAttributeMaxDynamicSharedMemorySize, edge_smem);
    cudaFuncSetAttribute(node_kernel, cudaFuncAttributeMaxDynamicSharedMemorySize, node_smem);

    detect_kernel<<<1, 32>>>((const unsigned*)ei);
    zero_kernel<<<512, NTHR>>>();
    precomp_kernel<<<dim3(NNODE / TILE, 2), NTHR, prec_smem>>>(h, e_w1);
    edge_kernel<<<NEDGE / TILE, NTHR, edge_smem>>>(x, ei,
                                                   e_w1, e_b1, e_w2, e_b2,
                                                   c_w1, c_b1, c_w2);
    node_kernel<<<NNODE / TILE, NTHR, node_smem>>>(h, n_w1, n_b1, n_w2, n_b2,
                                                   ln_g, ln_b, out);
    xnew_kernel<<<(NNODE * 3 + NTHR - 1) / NTHR, NTHR>>>(x, out + NNODE * HDIM);
}

// round 5
// speedup vs baseline: 2.4382x; 1.1604x over previous
#include <cuda_runtime.h>

// ---------------------------------------------------------------------------
// EGNN layer: N=20000 nodes, E=320000 edges, H=256.
// Round 5: 2-D register tiling (4 features x 8 edges per thread) for the
// GEMM phases. Per k-step: 2 broadcast-free LDS.128 + 1 coalesced LDG.128
// + 16 FFMA2, replacing 8 broadcast LDS.128 (L1 crossbar was 96% busy).
// ---------------------------------------------------------------------------

#define HDIM    256
#define NNODE   20000
#define NEDGE   320000
#define TILE    32
#define NTHR    256
#define STR     36          // smem row stride in floats (144B, 16B aligned)
#define CHUNK   128         // K-rows staged per chunk
#define LN_EPS  1e-5f

// scratch (device globals: allocation-free per harness rules)
__device__ float g_msg[NNODE * HDIM];     // 20.5 MB
__device__ float g_P[NNODE * HDIM];       // h @ W1[0:256]
__device__ float g_Q[NNODE * HDIM];       // h @ W1[256:512]
__device__ float g_coord[NNODE * 3];
__device__ int   g_is64;                  // 1 if edge_index is int64

__device__ __forceinline__ float silu_f(float v) {
    return v / (1.0f + __expf(-v));
}

__device__ __forceinline__ unsigned long long pack2(float a, float b) {
    unsigned long long r;
    asm("mov.b64 %0, {%1, %2};" : "=l"(r) : "f"(a), "f"(b));
    return r;
}
__device__ __forceinline__ float2 unpack2(unsigned long long v) {
    float2 r;
    asm("mov.b64 {%0, %1}, %2;" : "=f"(r.x), "=f"(r.y) : "l"(v));
    return r;
}
#define FFMA2(acc, v, w) \
    asm("fma.rn.f32x2 %0, %1, %2, %0;" : "+l"(acc) : "l"(v), "l"(w))

// 16 FFMA2: acc[j][p] += edgepair_p * (w_j, w_j)
#define GEMM_STEP(acc, row, wf4)                                             \
    do {                                                                     \
        ulonglong2 ea = *reinterpret_cast<const ulonglong2*>(row);           \
        ulonglong2 eb = *reinterpret_cast<const ulonglong2*>((row) + 4);     \
        unsigned long long wp0 = pack2((wf4).x, (wf4).x);                    \
        unsigned long long wp1 = pack2((wf4).y, (wf4).y);                    \
        unsigned long long wp2 = pack2((wf4).z, (wf4).z);                    \
        unsigned long long wp3 = pack2((wf4).w, (wf4).w);                    \
        FFMA2(acc[0][0], ea.x, wp0); FFMA2(acc[0][1], ea.y, wp0);            \
        FFMA2(acc[0][2], eb.x, wp0); FFMA2(acc[0][3], eb.y, wp0);            \
        FFMA2(acc[1][0], ea.x, wp1); FFMA2(acc[1][1], ea.y, wp1);            \
        FFMA2(acc[1][2], eb.x, wp1); FFMA2(acc[1][3], eb.y, wp1);            \
        FFMA2(acc[2][0], ea.x, wp2); FFMA2(acc[2][1], ea.y, wp2);            \
        FFMA2(acc[2][2], eb.x, wp2); FFMA2(acc[2][3], eb.y, wp2);            \
        FFMA2(acc[3][0], ea.x, wp3); FFMA2(acc[3][1], ea.y, wp3);            \
        FFMA2(acc[3][2], eb.x, wp3); FFMA2(acc[3][3], eb.y, wp3);            \
    } while (0)

// ---------------------------------------------------------------------------
__global__ void detect_kernel(const unsigned* __restrict__ w) {
    unsigned acc = 0;
    for (int i = threadIdx.x; i < 1024; i += 32) acc |= w[2 * i + 1];
    #pragma unroll
    for (int o = 16; o; o >>= 1) acc |= __shfl_xor_sync(0xFFFFFFFFu, acc, o);
    if (threadIdx.x == 0) g_is64 = (acc == 0) ? 1 : 0;
}

// ---------------------------------------------------------------------------
__global__ void zero_kernel() {
    int i = blockIdx.x * blockDim.x + threadIdx.x;
    int stride = gridDim.x * blockDim.x;
    for (int idx = i; idx < NNODE * HDIM; idx += stride) g_msg[idx] = 0.0f;
    for (int idx = i; idx < NNODE * 3;    idx += stride) g_coord[idx] = 0.0f;
}

// ---------------------------------------------------------------------------
// Precompute kernel: P = h @ W1[0:256], Q = h @ W1[256:512].
// ---------------------------------------------------------------------------
extern __shared__ float smem_p[];

__global__ __launch_bounds__(NTHR, 3)
void precomp_kernel(const float* __restrict__ h, const float* __restrict__ W1)
{
    float* s_buf = smem_p;                  // CHUNK * 36

    const int tid  = threadIdx.x;
    const int n0   = blockIdx.x * TILE;
    const int side = blockIdx.y;
    const float* W = W1 + side * HDIM * HDIM;
    float* out = side ? g_Q : g_P;
    const int fg = tid >> 2, eg = tid & 3;
    const int f0 = fg * 4, nl = eg * 8;

    unsigned long long acc[4][4];
    #pragma unroll
    for (int j = 0; j < 4; j++)
        #pragma unroll
        for (int p = 0; p < 4; p++) acc[j][p] = 0ULL;

    for (int c0 = 0; c0 < HDIM; c0 += CHUNK) {
        __syncthreads();
        for (int idx = tid; idx < TILE * CHUNK; idx += NTHR) {
            int n = idx >> 7;
            int k = idx & (CHUNK - 1);
            s_buf[k * STR + n] = h[(n0 + n) * HDIM + c0 + k];
        }
        __syncthreads();
        #pragma unroll 2
        for (int k = 0; k < CHUNK; k++) {
            float4 w = *reinterpret_cast<const float4*>(&W[(c0 + k) * HDIM + f0]);
            const float* row = &s_buf[k * STR + nl];
            GEMM_STEP(acc, row, w);
        }
    }
    #pragma unroll
    for (int j = 0; j < 4; j++) {
        #pragma unroll
        for (int p = 0; p < 4; p++) {
            float2 a = unpack2(acc[j][p]);
            out[(n0 + nl + 2 * p + 0) * HDIM + f0 + j] = a.x;
            out[(n0 + nl + 2 * p + 1) * HDIM + f0 + j] = a.y;
        }
    }
}

// ---------------------------------------------------------------------------
// Edge kernel: one block = 32 edges.
// Phase B (gather): thread = feature. Phases D/E: 4 feat x 8 edge tiles.
// ---------------------------------------------------------------------------
extern __shared__ float smem_e[];

__global__ __launch_bounds__(NTHR, 3)
void edge_kernel(const float* __restrict__ x,
                 const void* __restrict__ ei_raw,
                 const float* __restrict__ W1, const float* __restrict__ b1,
                 const float* __restrict__ W2, const float* __restrict__ b2,
                 const float* __restrict__ C1, const float* __restrict__ cb1,
                 const float* __restrict__ C2)
{
    float* s_m    = smem_e;                 // 256 * 36 = 9216 (m / m_ij)
    float* s_dist = s_m + 256 * STR;        // 32
    float* s_diff = s_dist + 32;            // 96
    float* s_red  = s_diff + 96;            // 256
    int*   s_row  = (int*)(s_red + 256);    // 32
    int*   s_col  = s_row + 32;             // 32

    const int tid = threadIdx.x;
    const int e0  = blockIdx.x * TILE;
    const int fg = tid >> 2, eg = tid & 3;
    const int f0 = fg * 4, el = eg * 8;
    const int lane = tid & 31, wrp = tid >> 5;

    if (tid < TILE) {
        int e = e0 + tid;
        int r, c;
        if (g_is64) {
            const long long* p = (const long long*)ei_raw;
            r = (int)p[e];
            c = (int)p[NEDGE + e];
        } else {
            const int* p = (const int*)ei_raw;
            r = p[e];
            c = p[NEDGE + e];
        }
        s_row[tid] = r;
        s_col[tid] = c;
        float dx = x[r * 3 + 0] - x[c * 3 + 0];
        float dy = x[r * 3 + 1] - x[c * 3 + 1];
        float dz = x[r * 3 + 2] - x[c * 3 + 2];
        s_diff[tid * 3 + 0] = dx;
        s_diff[tid * 3 + 1] = dy;
        s_diff[tid * 3 + 2] = dz;
        s_dist[tid] = dx * dx + dy * dy + dz * dz;
    }
    __syncthreads();

    // ---- phase B (gather): m[j][e] = silu(P[row]+Q[col]+dist*w1d+b1) ----
    {
        float w1d = W1[512 * HDIM + tid];
        float b1j = b1[tid];
        #pragma unroll 4
        for (int e = 0; e < TILE; e++) {
            int r = s_row[e], c = s_col[e];
            float v = g_P[r * HDIM + tid] + g_Q[c * HDIM + tid] + b1j;
            v = fmaf(s_dist[e], w1d, v);
            s_m[tid * STR + e] = silu_f(v);
        }
    }
    __syncthreads();

    unsigned long long acc[4][4];

    // ---- phase D: m_ij = silu(m @ W2 + b2); scatter to g_msg ----
    {
        float4 bv = *reinterpret_cast<const float4*>(&b2[f0]);
        acc[0][0] = acc[0][1] = acc[0][2] = acc[0][3] = pack2(bv.x, bv.x);
        acc[1][0] = acc[1][1] = acc[1][2] = acc[1][3] = pack2(bv.y, bv.y);
        acc[2][0] = acc[2][1] = acc[2][2] = acc[2][3] = pack2(bv.z, bv.z);
        acc[3][0] = acc[3][1] = acc[3][2] = acc[3][3] = pack2(bv.w, bv.w);
        #pragma unroll 2
        for (int k = 0; k < HDIM; k++) {
            float4 w = *reinterpret_cast<const float4*>(&W2[k * HDIM + f0]);
            const float* row = &s_m[k * STR + el];
            GEMM_STEP(acc, row, w);
        }
        __syncthreads();   // all reads of m done before overwrite
        #pragma unroll
        for (int j = 0; j < 4; j++) {
            #pragma unroll
            for (int p = 0; p < 4; p++) {
                float2 a = unpack2(acc[j][p]);
                a.x = silu_f(a.x);
                a.y = silu_f(a.y);
                // STS.64: m_ij overwrites m
                *reinterpret_cast<float2*>(&s_m[(f0 + j) * STR + el + 2 * p]) = a;
            }
        }
        __syncthreads();
        // coalesced scatter (thread = feature): for fixed e, 256 consecutive
        #pragma unroll 4
        for (int e = 0; e < TILE; e++)
            atomicAdd(&g_msg[s_col[e] * HDIM + tid], s_m[tid * STR + e]);
    }

    // ---- phase E: coord_weight = silu(m_ij @ C1 + cb1) @ C2 ----
    {
        float4 bv = *reinterpret_cast<const float4*>(&cb1[f0]);
        float4 c2 = *reinterpret_cast<const float4*>(&C2[f0]);
        acc[0][0] = acc[0][1] = acc[0][2] = acc[0][3] = pack2(bv.x, bv.x);
        acc[1][0] = acc[1][1] = acc[1][2] = acc[1][3] = pack2(bv.y, bv.y);
        acc[2][0] = acc[2][1] = acc[2][2] = acc[2][3] = pack2(bv.z, bv.z);
        acc[3][0] = acc[3][1] = acc[3][2] = acc[3][3] = pack2(bv.w, bv.w);
        #pragma unroll 2
        for (int k = 0; k < HDIM; k++) {
            float4 w = *reinterpret_cast<const float4*>(&C1[k * HDIM + f0]);
            const float* row = &s_m[k * STR + el];
            GEMM_STEP(acc, row, w);
        }
        // per-thread partials over its 4 features, for its 8 edges
        float pe[8];
        #pragma unroll
        for (int p = 0; p < 4; p++) {
            float2 a0 = unpack2(acc[0][p]);
            float2 a1 = unpack2(acc[1][p]);
            float2 a2 = unpack2(acc[2][p]);
            float2 a3 = unpack2(acc[3][p]);
            pe[2 * p + 0] = silu_f(a0.x) * c2.x + silu_f(a1.x) * c2.y
                          + silu_f(a2.x) * c2.z + silu_f(a3.x) * c2.w;
            pe[2 * p + 1] = silu_f(a0.y) * c2.x + silu_f(a1.y) * c2.y
                          + silu_f(a2.y) * c2.z + silu_f(a3.y) * c2.w;
        }
        // reduce across the 8 feature-groups within the warp (same eg)
        #pragma unroll
        for (int i = 0; i < 8; i++) {
            pe[i] += __shfl_xor_sync(0xFFFFFFFFu, pe[i], 4);
            pe[i] += __shfl_xor_sync(0xFFFFFFFFu, pe[i], 8);
            pe[i] += __shfl_xor_sync(0xFFFFFFFFu, pe[i], 16);
        }
        if (lane < 4) {
            #pragma unroll
            for (int i = 0; i < 8; i++)
                s_red[(lane * 8 + i) * 8 + wrp] = pe[i];
        }
        __syncthreads();
        if (tid < TILE) {
            float wsum = 0.0f;
            #pragma unroll
            for (int i = 0; i < 8; i++) wsum += s_red[tid * 8 + i];
            int c = s_col[tid];
            atomicAdd(&g_coord[c * 3 + 0], wsum * s_diff[tid * 3 + 0]);
            atomicAdd(&g_coord[c * 3 + 1], wsum * s_diff[tid * 3 + 1]);
            atomicAdd(&g_coord[c * 3 + 2], wsum * s_diff[tid * 3 + 2]);
        }
    }
}

// ---------------------------------------------------------------------------
// Node kernel: one block = 32 nodes. node MLP + residual + LayerNorm.
// ---------------------------------------------------------------------------
extern __shared__ float smem_n[];

__global__ __launch_bounds__(NTHR, 3)
void node_kernel(const float* __restrict__ h,
                 const float* __restrict__ NW1, const float* __restrict__ nb1,
                 const float* __restrict__ NW2, const float* __restrict__ nb2,
                 const float* __restrict__ lng, const float* __restrict__ lnb,
                 float* __restrict__ out_h)
{
    float* s_buf = smem_n;                  // CHUNK * 36 = 4608 (staging)
    float* s_u   = s_buf + CHUNK * STR;     // 256 * 36   = 9216
    float* s_r1  = s_u + 256 * STR;         // 256
    float* s_r2  = s_r1 + 256;              // 256
    float* s_mu  = s_r2 + 256;              // 32
    float* s_rs  = s_mu + 32;               // 32

    const int tid = threadIdx.x;
    const int n0  = blockIdx.x * TILE;
    const int fg = tid >> 2, eg = tid & 3;
    const int f0 = fg * 4, nl = eg * 8;
    const int lane = tid & 31, wrp = tid >> 5;

    unsigned long long acc[4][4];

    // ---- u = silu(h_cat @ NW1 + nb1), K = 512 chunked ----
    {
        float4 bv = *reinterpret_cast<const float4*>(&nb1[f0]);
        acc[0][0] = acc[0][1] = acc[0][2] = acc[0][3] = pack2(bv.x, bv.x);
        acc[1][0] = acc[1][1] = acc[1][2] = acc[1][3] = pack2(bv.y, bv.y);
        acc[2][0] = acc[2][1] = acc[2][2] = acc[2][3] = pack2(bv.z, bv.z);
        acc[3][0] = acc[3][1] = acc[3][2] = acc[3][3] = pack2(bv.w, bv.w);

        for (int c0 = 0; c0 < 512; c0 += CHUNK) {
            __syncthreads();
            for (int idx = tid; idx < TILE * CHUNK; idx += NTHR) {
                int n = idx >> 7;
                int k = idx & (CHUNK - 1);
                int kk = c0 + k;
                int node = n0 + n;
                float v = (kk < HDIM) ? h[node * HDIM + kk]
                                      : g_msg[node * HDIM + (kk - HDIM)];
                s_buf[k * STR + n] = v;
            }
            __syncthreads();
            #pragma unroll 2
            for (int k = 0; k < CHUNK; k++) {
                float4 w = *reinterpret_cast<const float4*>(&NW1[(c0 + k) * HDIM + f0]);
                const float* row = &s_buf[k * STR + nl];
                GEMM_STEP(acc, row, w);
            }
        }
        #pragma unroll
        for (int j = 0; j < 4; j++) {
            #pragma unroll
            for (int p = 0; p < 4; p++) {
                float2 a = unpack2(acc[j][p]);
                a.x = silu_f(a.x);
                a.y = silu_f(a.y);
                *reinterpret_cast<float2*>(&s_u[(f0 + j) * STR + nl + 2 * p]) = a;
            }
        }
    }
    __syncthreads();

    // ---- y = u @ NW2 + nb2 + h ; LayerNorm ----
    {
        float4 bv = *reinterpret_cast<const float4*>(&nb2[f0]);
        acc[0][0] = acc[0][1] = acc[0][2] = acc[0][3] = pack2(bv.x, bv.x);
        acc[1][0] = acc[1][1] = acc[1][2] = acc[1][3] = pack2(bv.y, bv.y);
        acc[2][0] = acc[2][1] = acc[2][2] = acc[2][3] = pack2(bv.z, bv.z);
        acc[3][0] = acc[3][1] = acc[3][2] = acc[3][3] = pack2(bv.w, bv.w);
        #pragma unroll 2
        for (int k = 0; k < HDIM; k++) {
            float4 w = *reinterpret_cast<const float4*>(&NW2[k * HDIM + f0]);
            const float* row = &s_u[k * STR + nl];
            GEMM_STEP(acc, row, w);
        }

        // y[j][i]: feature f0+j, node n0+nl+i ; add residual h
        float y[4][8];
        #pragma unroll
        for (int i = 0; i < 8; i++) {
            float4 hv = *reinterpret_cast<const float4*>(&h[(n0 + nl + i) * HDIM + f0]);
            int p = i >> 1, hi = i & 1;
            float2 a0 = unpack2(acc[0][p]);
            float2 a1 = unpack2(acc[1][p]);
            float2 a2 = unpack2(acc[2][p]);
            float2 a3 = unpack2(acc[3][p]);
            y[0][i] = (hi ? a0.y : a0.x) + hv.x;
            y[1][i] = (hi ? a1.y : a1.x) + hv.y;
            y[2][i] = (hi ? a2.y : a2.x) + hv.z;
            y[3][i] = (hi ? a3.y : a3.x) + hv.w;
        }
        // per-node partial sums over this thread's 4 features
        float p1[8], p2[8];
        #pragma unroll
        for (int i = 0; i < 8; i++) {
            p1[i] = y[0][i] + y[1][i] + y[2][i] + y[3][i];
            p2[i] = y[0][i] * y[0][i] + y[1][i] * y[1][i]
                  + y[2][i] * y[2][i] + y[3][i] * y[3][i];
        }
        #pragma unroll
        for (int i = 0; i < 8; i++) {
            #pragma unroll
            for (int o = 4; o <= 16; o <<= 1) {
                p1[i] += __shfl_xor_sync(0xFFFFFFFFu, p1[i], o);
                p2[i] += __shfl_xor_sync(0xFFFFFFFFu, p2[i], o);
            }
        }
        if (lane < 4) {
            #pragma unroll
            for (int i = 0; i < 8; i++) {
                s_r1[(lane * 8 + i) * 8 + wrp] = p1[i];
                s_r2[(lane * 8 + i) * 8 + wrp] = p2[i];
            }
        }
        __syncthreads();
        if (tid < TILE) {
            float S1 = 0.0f, S2 = 0.0f;
            #pragma unroll
            for (int i = 0; i < 8; i++) { S1 += s_r1[tid * 8 + i]; S2 += s_r2[tid * 8 + i]; }
            float mu  = S1 * (1.0f / HDIM);
            float var = S2 * (1.0f / HDIM) - mu * mu;
            s_mu[tid] = mu;
            s_rs[tid] = rsqrtf(var + LN_EPS);
        }
        __syncthreads();
        float4 gv = *reinterpret_cast<const float4*>(&lng[f0]);
        float4 bb = *reinterpret_cast<const float4*>(&lnb[f0]);
        #pragma unroll
        for (int i = 0; i < 8; i++) {
            float mu = s_mu[nl + i], rs = s_rs[nl + i];
            float4 o;
            o.x = (y[0][i] - mu) * rs * gv.x + bb.x;
            o.y = (y[1][i] - mu) * rs * gv.y + bb.y;
            o.z = (y[2][i] - mu) * rs * gv.z + bb.z;
            o.w = (y[3][i] - mu) * rs * gv.w + bb.w;
            *reinterpret_cast<float4*>(&out_h[(n0 + nl + i) * HDIM + f0]) = o;
        }
    }
}

// ---------------------------------------------------------------------------
__global__ void xnew_kernel(const float* __restrict__ x, float* __restrict__ out_x) {
    int i = blockIdx.x * blockDim.x + threadIdx.x;
    if (i < NNODE * 3) out_x[i] = x[i] + g_coord[i];
}

// ---------------------------------------------------------------------------
extern "C" void kernel_launch(void* const* d_in, const int* in_sizes, int n_in,
                              void* d_out, int out_size)
{
    const float* h    = (const float*)d_in[0];
    const float* x    = (const float*)d_in[1];
    const void*  ei   = d_in[2];
    const float* e_w1 = (const float*)d_in[3];
    const float* e_b1 = (const float*)d_in[4];
    const float* e_w2 = (const float*)d_in[5];
    const float* e_b2 = (const float*)d_in[6];
    const float* c_w1 = (const float*)d_in[7];
    const float* c_b1 = (const float*)d_in[8];
    const float* c_w2 = (const float*)d_in[9];
    const float* n_w1 = (const float*)d_in[10];
    const float* n_b1 = (const float*)d_in[11];
    const float* n_w2 = (const float*)d_in[12];
    const float* n_b2 = (const float*)d_in[13];
    const float* ln_g = (const float*)d_in[14];
    const float* ln_b = (const float*)d_in[15];
    float* out = (float*)d_out;

    const int prec_smem = (CHUNK * STR) * 4;
    const int edge_smem = (256 * STR + 32 + 96 + 256 + 64) * 4;
    const int node_smem = (CHUNK * STR + 256 * STR + 256 + 256 + 32 + 32) * 4;

    cudaFuncSetAttribute(precomp_kernel, cudaFuncAttributeMaxDynamicSharedMemorySize, prec_smem);
    cudaFuncSetAttribute(edge_kernel, cudaFuncAttributeMaxDynamicSharedMemorySize, edge_smem);
    cudaFuncSetAttribute(node_kernel, cudaFuncAttributeMaxDynamicSharedMemorySize, node_smem);

    detect_kernel<<<1, 32>>>((const unsigned*)ei);
    zero_kernel<<<512, NTHR>>>();
    precomp_kernel<<<dim3(NNODE / TILE, 2), NTHR, prec_smem>>>(h, e_w1);
    edge_kernel<<<NEDGE / TILE, NTHR, edge_smem>>>(x, ei,
                                                   e_w1, e_b1, e_w2, e_b2,
                                                   c_w1, c_b1, c_w2);
    node_kernel<<<NNODE / TILE, NTHR, node_smem>>>(h, n_w1, n_b1, n_w2, n_b2,
                                                   ln_g, ln_b, out);
    xnew_kernel<<<(NNODE * 3 + NTHR - 1) / NTHR, NTHR>>>(x, out + NNODE * HDIM);
}

// round 7
// speedup vs baseline: 3.6461x; 1.4954x over previous
#include <cuda_runtime.h>
#include <cstdint>

// ---------------------------------------------------------------------------
// EGNN layer: N=20000 nodes, E=320000 edges, H=256.
// Round 7: edge GEMMs via warp-level mma.sync tf32 (baseline PTX, no 'a'
// feature needed — tcgen05 is blocked by harness's sm_103 ptx target).
// ---------------------------------------------------------------------------

#define HDIM    256
#define NNODE   20000
#define NEDGE   320000
#define TILE    32
#define NTHR    256
#define STR     36
#define CHUNK   128
#define LN_EPS  1e-5f

#define ET      64           // edges per edge-MMA block
#define ETHR    512          // threads (16 warps: 4M x 4N)

// edge kernel smem layout (float offsets)
#define O_M     0            // s_m  [64][260]           = 16640
#define O_B0    16640        // B buf0 [256][36]         =  9216
#define O_B1    25856        // B buf1                   =  9216
#define O_ROW   35072        // 64 int
#define O_COL   35136        // 64 int
#define O_DIST  35200        // 64 f
#define O_DIFF  35264        // 192 f
#define O_RED   35456        // 64*4 f
#define EDGE_SMEM ((35456 + 256) * 4)

__device__ float g_msg[NNODE * HDIM];
__device__ float g_P[NNODE * HDIM];
__device__ float g_Q[NNODE * HDIM];
__device__ float g_coord[NNODE * 3];
__device__ float g_W2t[HDIM * HDIM];   // W2^T [n][k], tf32-rounded
__device__ float g_C1t[HDIM * HDIM];   // C1^T [n][k], tf32-rounded
__device__ int   g_is64;

__device__ __forceinline__ float silu_f(float v) {
    return v / (1.0f + __expf(-v));
}
__device__ __forceinline__ uint32_t tf32_bits(float x) {
    uint32_t u;
    asm("cvt.rna.tf32.f32 %0, %1;" : "=r"(u) : "f"(x));
    return u;
}
__device__ __forceinline__ float tf32r(float x) {
    return __uint_as_float(tf32_bits(x));
}
__device__ __forceinline__ uint32_t smem_u32(const void* p) {
    uint32_t a;
    asm("{ .reg .u64 t; cvta.to.shared.u64 t, %1; cvt.u32.u64 %0, t; }"
        : "=r"(a) : "l"(p));
    return a;
}
__device__ __forceinline__ unsigned long long pack2(float a, float b) {
    unsigned long long r;
    asm("mov.b64 %0, {%1, %2};" : "=l"(r) : "f"(a), "f"(b));
    return r;
}
__device__ __forceinline__ float2 unpack2(unsigned long long v) {
    float2 r;
    asm("mov.b64 {%0, %1}, %2;" : "=f"(r.x), "=f"(r.y) : "l"(v));
    return r;
}
#define FFMA2(acc, v, w) \
    asm("fma.rn.f32x2 %0, %1, %2, %0;" : "+l"(acc) : "l"(v), "l"(w))

#define GEMM_STEP(acc, row, wf4)                                             \
    do {                                                                     \
        ulonglong2 ea = *reinterpret_cast<const ulonglong2*>(row);           \
        ulonglong2 eb = *reinterpret_cast<const ulonglong2*>((row) + 4);     \
        unsigned long long wp0 = pack2((wf4).x, (wf4).x);                    \
        unsigned long long wp1 = pack2((wf4).y, (wf4).y);                    \
        unsigned long long wp2 = pack2((wf4).z, (wf4).z);                    \
        unsigned long long wp3 = pack2((wf4).w, (wf4).w);                    \
        FFMA2(acc[0][0], ea.x, wp0); FFMA2(acc[0][1], ea.y, wp0);            \
        FFMA2(acc[0][2], eb.x, wp0); FFMA2(acc[0][3], eb.y, wp0);            \
        FFMA2(acc[1][0], ea.x, wp1); FFMA2(acc[1][1], ea.y, wp1);            \
        FFMA2(acc[1][2], eb.x, wp1); FFMA2(acc[1][3], eb.y, wp1);            \
        FFMA2(acc[2][0], ea.x, wp2); FFMA2(acc[2][1], ea.y, wp2);            \
        FFMA2(acc[2][2], eb.x, wp2); FFMA2(acc[2][3], eb.y, wp2);            \
        FFMA2(acc[3][0], ea.x, wp3); FFMA2(acc[3][1], ea.y, wp3);            \
        FFMA2(acc[3][2], eb.x, wp3); FFMA2(acc[3][3], eb.y, wp3);            \
    } while (0)

// ---------------------------------------------------------------------------
__global__ void detect_kernel(const unsigned* __restrict__ w) {
    unsigned acc = 0;
    for (int i = threadIdx.x; i < 1024; i += 32) acc |= w[2 * i + 1];
    #pragma unroll
    for (int o = 16; o; o >>= 1) acc |= __shfl_xor_sync(0xFFFFFFFFu, acc, o);
    if (threadIdx.x == 0) g_is64 = (acc == 0) ? 1 : 0;
}

__global__ void zero_kernel() {
    int i = blockIdx.x * blockDim.x + threadIdx.x;
    int stride = gridDim.x * blockDim.x;
    for (int idx = i; idx < NNODE * HDIM; idx += stride) g_msg[idx] = 0.0f;
    for (int idx = i; idx < NNODE * 3;    idx += stride) g_coord[idx] = 0.0f;
}

// transpose + tf32-round W2, C1 -> g_W2t, g_C1t  ([n][k] = round(src[k][n]))
__global__ void transpose_kernel(const float* __restrict__ W2,
                                 const float* __restrict__ C1) {
    __shared__ float t[32][33];
    const float* src = blockIdx.z ? C1 : W2;
    float* dst = blockIdx.z ? g_C1t : g_W2t;
    int bx = blockIdx.x * 32, by = blockIdx.y * 32;
    int tx = threadIdx.x, ty = threadIdx.y;
    #pragma unroll
    for (int i = 0; i < 32; i += 8)
        t[ty + i][tx] = src[(by + ty + i) * HDIM + bx + tx];
    __syncthreads();
    #pragma unroll
    for (int i = 0; i < 32; i += 8)
        dst[(bx + ty + i) * HDIM + by + tx] = tf32r(t[tx][ty + i]);
}

// ---------------------------------------------------------------------------
// Precompute P = h @ W1[0:256], Q = h @ W1[256:512]  (SIMT f32x2, exact fp32)
// ---------------------------------------------------------------------------
extern __shared__ float smem_p[];

__global__ __launch_bounds__(NTHR, 3)
void precomp_kernel(const float* __restrict__ h, const float* __restrict__ W1)
{
    float* s_buf = smem_p;
    const int tid  = threadIdx.x;
    const int n0   = blockIdx.x * TILE;
    const int side = blockIdx.y;
    const float* W = W1 + side * HDIM * HDIM;
    float* out = side ? g_Q : g_P;
    const int fg = tid >> 2, eg = tid & 3;
    const int f0 = fg * 4, nl = eg * 8;

    unsigned long long acc[4][4];
    #pragma unroll
    for (int j = 0; j < 4; j++)
        #pragma unroll
        for (int p = 0; p < 4; p++) acc[j][p] = 0ULL;

    for (int c0 = 0; c0 < HDIM; c0 += CHUNK) {
        __syncthreads();
        for (int idx = tid; idx < TILE * CHUNK; idx += NTHR) {
            int n = idx >> 7;
            int k = idx & (CHUNK - 1);
            s_buf[k * STR + n] = h[(n0 + n) * HDIM + c0 + k];
        }
        __syncthreads();
        #pragma unroll 2
        for (int k = 0; k < CHUNK; k++) {
            float4 w = *reinterpret_cast<const float4*>(&W[(c0 + k) * HDIM + f0]);
            const float* row = &s_buf[k * STR + nl];
            GEMM_STEP(acc, row, w);
        }
    }
    #pragma unroll
    for (int j = 0; j < 4; j++) {
        #pragma unroll
        for (int p = 0; p < 4; p++) {
            float2 a = unpack2(acc[j][p]);
            out[(n0 + nl + 2 * p + 0) * HDIM + f0 + j] = a.x;
            out[(n0 + nl + 2 * p + 1) * HDIM + f0 + j] = a.y;
        }
    }
}

// ---------------------------------------------------------------------------
// tf32 warp-MMA GEMM core: D[64e x 256n] += s_m[64e x 256k] @ Wt^T.
// Wt global [n][k] (pre-transposed, tf32-rounded). B streamed in 32-k chunks
// through two smem buffers via cp.async. Warp (mi,ni) owns 16e x 64n tile.
// ---------------------------------------------------------------------------
__device__ __forceinline__ void stage_chunk(const float* __restrict__ Wt,
                                            float* sbuf, int c, int tid)
{
    uint32_t dst = smem_u32(sbuf);
    const float* src = Wt + c * 32;
    #pragma unroll
    for (int it = 0; it < 4; it++) {
        int idx = it * ETHR + tid;        // 0..2047
        int n  = idx >> 3;
        int k4 = idx & 7;
        uint32_t daddr = dst + (uint32_t)(n * 36 + k4 * 4) * 4u;
        const float* saddr = src + n * HDIM + k4 * 4;
        asm volatile("cp.async.cg.shared.global [%0], [%1], 16;"
                     :: "r"(daddr), "l"(saddr));
    }
}

__device__ __forceinline__ void run_gemm(const float* __restrict__ Wt,
                                         const float* s_m, float* sb0, float* sb1,
                                         float d[8][4], int m0, int n0b,
                                         int g, int tig, int tid)
{
    stage_chunk(Wt, sb0, 0, tid);
    asm volatile("cp.async.commit_group;" ::: "memory");
    #pragma unroll 1
    for (int c = 0; c < 8; c++) {
        if (c < 7) {
            stage_chunk(Wt, (c & 1) ? sb0 : sb1, c + 1, tid);
            asm volatile("cp.async.commit_group;" ::: "memory");
            asm volatile("cp.async.wait_group 1;" ::: "memory");
        } else {
            asm volatile("cp.async.wait_group 0;" ::: "memory");
        }
        __syncthreads();
        const float* sb = (c & 1) ? sb1 : sb0;
        #pragma unroll
        for (int ks = 0; ks < 4; ks++) {
            int kk = c * 32 + ks * 8;
            uint32_t a0 = __float_as_uint(s_m[(m0 + g)     * 260 + kk + tig]);
            uint32_t a1 = __float_as_uint(s_m[(m0 + g + 8) * 260 + kk + tig]);
            uint32_t a2 = __float_as_uint(s_m[(m0 + g)     * 260 + kk + tig + 4]);
            uint32_t a3 = __float_as_uint(s_m[(m0 + g + 8) * 260 + kk + tig + 4]);
            #pragma unroll
            for (int nt = 0; nt < 8; nt++) {
                const float* bp = &sb[(n0b + nt * 8 + g) * 36 + ks * 8 + tig];
                uint32_t b0 = __float_as_uint(bp[0]);
                uint32_t b1 = __float_as_uint(bp[4]);
                asm volatile(
                    "mma.sync.aligned.m16n8k8.row.col.f32.tf32.tf32.f32 "
                    "{%0,%1,%2,%3}, {%4,%5,%6,%7}, {%8,%9}, {%0,%1,%2,%3};"
                    : "+f"(d[nt][0]), "+f"(d[nt][1]), "+f"(d[nt][2]), "+f"(d[nt][3])
                    : "r"(a0), "r"(a1), "r"(a2), "r"(a3), "r"(b0), "r"(b1));
            }
        }
        __syncthreads();
    }
}

// ---------------------------------------------------------------------------
// Edge kernel: one block = 64 edges, 512 threads, tf32 MMA GEMMs.
// ---------------------------------------------------------------------------
extern __shared__ float sme[];

__global__ __launch_bounds__(ETHR, 1)
void edge_mma_kernel(const float* __restrict__ x,
                     const void* __restrict__ ei_raw,
                     const float* __restrict__ W1, const float* __restrict__ b1,
                     const float* __restrict__ b2, const float* __restrict__ cb1,
                     const float* __restrict__ C2)
{
    float* s_m   = sme + O_M;
    float* sb0   = sme + O_B0;
    float* sb1   = sme + O_B1;
    int*   s_row = (int*)(sme + O_ROW);
    int*   s_col = (int*)(sme + O_COL);
    float* s_dist = sme + O_DIST;
    float* s_diff = sme + O_DIFF;
    float* s_red  = sme + O_RED;

    const int tid  = threadIdx.x;
    const int lane = tid & 31;
    const int wid  = tid >> 5;
    const int g    = lane >> 2;
    const int tig  = lane & 3;
    const int m0   = (wid >> 2) * 16;
    const int n0b  = (wid & 3) * 64;
    const int e0   = blockIdx.x * ET;

    if (tid < ET) {
        int e = e0 + tid;
        int r, c;
        if (g_is64) {
            const long long* p = (const long long*)ei_raw;
            r = (int)p[e];
            c = (int)p[NEDGE + e];
        } else {
            const int* p = (const int*)ei_raw;
            r = p[e];
            c = p[NEDGE + e];
        }
        s_row[tid] = r;
        s_col[tid] = c;
        float dx = x[r * 3 + 0] - x[c * 3 + 0];
        float dy = x[r * 3 + 1] - x[c * 3 + 1];
        float dz = x[r * 3 + 2] - x[c * 3 + 2];
        s_diff[tid * 3 + 0] = dx;
        s_diff[tid * 3 + 1] = dy;
        s_diff[tid * 3 + 2] = dz;
        s_dist[tid] = dx * dx + dy * dy + dz * dz;
    }
    __syncthreads();

    // ---- phase B: m = silu(P[row]+Q[col]+dist*w1d+b1) -> s_m (tf32) ----
    {
        int f  = tid & 255;
        int eh = tid >> 8;
        float w1d = W1[512 * HDIM + f];
        float b1f = b1[f];
        #pragma unroll 4
        for (int j = 0; j < 32; j++) {
            int e = eh * 32 + j;
            int r = s_row[e], c = s_col[e];
            float v = g_P[r * HDIM + f] + g_Q[c * HDIM + f] + b1f;
            v = fmaf(s_dist[e], w1d, v);
            s_m[e * 260 + f] = tf32r(silu_f(v));
        }
    }
    __syncthreads();

    float d[8][4];

    // ---- GEMM1: D = m @ W2 ----
    #pragma unroll
    for (int nt = 0; nt < 8; nt++)
        d[nt][0] = d[nt][1] = d[nt][2] = d[nt][3] = 0.0f;
    run_gemm(g_W2t, s_m, sb0, sb1, d, m0, n0b, g, tig, tid);

    // ---- readback1: m_ij = silu(D + b2) -> s_m (exact fp32) ----
    #pragma unroll
    for (int nt = 0; nt < 8; nt++) {
        int f0 = n0b + nt * 8 + 2 * tig;
        int er = m0 + g;
        float2 v01 = make_float2(silu_f(d[nt][0] + b2[f0]),
                                 silu_f(d[nt][1] + b2[f0 + 1]));
        float2 v23 = make_float2(silu_f(d[nt][2] + b2[f0]),
                                 silu_f(d[nt][3] + b2[f0 + 1]));
        *reinterpret_cast<float2*>(&s_m[er * 260 + f0])       = v01;
        *reinterpret_cast<float2*>(&s_m[(er + 8) * 260 + f0]) = v23;
    }
    __syncthreads();

    // ---- scatter exact m_ij to g_msg; convert s_m to tf32 for GEMM2 ----
    {
        int f4 = (tid & 63) * 4;
        int eh = tid >> 6;                 // 0..7
        #pragma unroll
        for (int j = 0; j < 8; j++) {
            int e = eh * 8 + j;
            float4 v = *reinterpret_cast<float4*>(&s_m[e * 260 + f4]);
            atomicAdd(reinterpret_cast<float4*>(&g_msg[s_col[e] * HDIM + f4]), v);
            v.x = tf32r(v.x); v.y = tf32r(v.y); v.z = tf32r(v.z); v.w = tf32r(v.w);
            *reinterpret_cast<float4*>(&s_m[e * 260 + f4]) = v;
        }
    }
    __syncthreads();

    // ---- GEMM2: D = m_ij @ C1 ----
    #pragma unroll
    for (int nt = 0; nt < 8; nt++)
        d[nt][0] = d[nt][1] = d[nt][2] = d[nt][3] = 0.0f;
    run_gemm(g_C1t, s_m, sb0, sb1, d, m0, n0b, g, tig, tid);

    // ---- readback2: coord_weight = sum_f silu(D + cb1) * C2 ----
    {
        float cw0 = 0.0f, cw8 = 0.0f;
        #pragma unroll
        for (int nt = 0; nt < 8; nt++) {
            int f0 = n0b + nt * 8 + 2 * tig;
            float c20 = C2[f0], c21 = C2[f0 + 1];
            float bb0 = cb1[f0], bb1 = cb1[f0 + 1];
            cw0 += silu_f(d[nt][0] + bb0) * c20 + silu_f(d[nt][1] + bb1) * c21;
            cw8 += silu_f(d[nt][2] + bb0) * c20 + silu_f(d[nt][3] + bb1) * c21;
        }
        cw0 += __shfl_xor_sync(0xFFFFFFFFu, cw0, 1);
        cw0 += __shfl_xor_sync(0xFFFFFFFFu, cw0, 2);
        cw8 += __shfl_xor_sync(0xFFFFFFFFu, cw8, 1);
        cw8 += __shfl_xor_sync(0xFFFFFFFFu, cw8, 2);
        if (tig == 0) {
            s_red[(m0 + g) * 4 + (wid & 3)]     = cw0;
            s_red[(m0 + g + 8) * 4 + (wid & 3)] = cw8;
        }
    }
    __syncthreads();
    if (tid < ET) {
        float w = s_red[tid * 4] + s_red[tid * 4 + 1]
                + s_red[tid * 4 + 2] + s_red[tid * 4 + 3];
        int c = s_col[tid];
        atomicAdd(&g_coord[c * 3 + 0], w * s_diff[tid * 3 + 0]);
        atomicAdd(&g_coord[c * 3 + 1], w * s_diff[tid * 3 + 1]);
        atomicAdd(&g_coord[c * 3 + 2], w * s_diff[tid * 3 + 2]);
    }
}

// ---------------------------------------------------------------------------
// Node kernel (SIMT f32x2, exact): one block = 32 nodes.
// ---------------------------------------------------------------------------
extern __shared__ float smem_n[];

__global__ __launch_bounds__(NTHR, 3)
void node_kernel(const float* __restrict__ h,
                 const float* __restrict__ NW1, const float* __restrict__ nb1,
                 const float* __restrict__ NW2, const float* __restrict__ nb2,
                 const float* __restrict__ lng, const float* __restrict__ lnb,
                 float* __restrict__ out_h)
{
    float* s_buf = smem_n;
    float* s_u   = s_buf + CHUNK * STR;
    float* s_r1  = s_u + 256 * STR;
    float* s_r2  = s_r1 + 256;
    float* s_mu  = s_r2 + 256;
    float* s_rs  = s_mu + 32;

    const int tid = threadIdx.x;
    const int n0  = blockIdx.x * TILE;
    const int fg = tid >> 2, eg = tid & 3;
    const int f0 = fg * 4, nl = eg * 8;
    const int lane = tid & 31, wrp = tid >> 5;

    unsigned long long acc[4][4];

    {
        float4 bv = *reinterpret_cast<const float4*>(&nb1[f0]);
        acc[0][0] = acc[0][1] = acc[0][2] = acc[0][3] = pack2(bv.x, bv.x);
        acc[1][0] = acc[1][1] = acc[1][2] = acc[1][3] = pack2(bv.y, bv.y);
        acc[2][0] = acc[2][1] = acc[2][2] = acc[2][3] = pack2(bv.z, bv.z);
        acc[3][0] = acc[3][1] = acc[3][2] = acc[3][3] = pack2(bv.w, bv.w);

        for (int c0 = 0; c0 < 512; c0 += CHUNK) {
            __syncthreads();
            for (int idx = tid; idx < TILE * CHUNK; idx += NTHR) {
                int n = idx >> 7;
                int k = idx & (CHUNK - 1);
                int kk = c0 + k;
                int node = n0 + n;
                float v = (kk < HDIM) ? h[node * HDIM + kk]
                                      : g_msg[node * HDIM + (kk - HDIM)];
                s_buf[k * STR + n] = v;
            }
            __syncthreads();
            #pragma unroll 2
            for (int k = 0; k < CHUNK; k++) {
                float4 w = *reinterpret_cast<const float4*>(&NW1[(c0 + k) * HDIM + f0]);
                const float* row = &s_buf[k * STR + nl];
                GEMM_STEP(acc, row, w);
            }
        }
        #pragma unroll
        for (int j = 0; j < 4; j++) {
            #pragma unroll
            for (int p = 0; p < 4; p++) {
                float2 a = unpack2(acc[j][p]);
                a.x = silu_f(a.x);
                a.y = silu_f(a.y);
                *reinterpret_cast<float2*>(&s_u[(f0 + j) * STR + nl + 2 * p]) = a;
            }
        }
    }
    __syncthreads();

    {
        float4 bv = *reinterpret_cast<const float4*>(&nb2[f0]);
        acc[0][0] = acc[0][1] = acc[0][2] = acc[0][3] = pack2(bv.x, bv.x);
        acc[1][0] = acc[1][1] = acc[1][2] = acc[1][3] = pack2(bv.y, bv.y);
        acc[2][0] = acc[2][1] = acc[2][2] = acc[2][3] = pack2(bv.z, bv.z);
        acc[3][0] = acc[3][1] = acc[3][2] = acc[3][3] = pack2(bv.w, bv.w);
        #pragma unroll 2
        for (int k = 0; k < HDIM; k++) {
            float4 w = *reinterpret_cast<const float4*>(&NW2[k * HDIM + f0]);
            const float* row = &s_u[k * STR + nl];
            GEMM_STEP(acc, row, w);
        }

        float y[4][8];
        #pragma unroll
        for (int i = 0; i < 8; i++) {
            float4 hv = *reinterpret_cast<const float4*>(&h[(n0 + nl + i) * HDIM + f0]);
            int p = i >> 1, hi = i & 1;
            float2 a0 = unpack2(acc[0][p]);
            float2 a1 = unpack2(acc[1][p]);
            float2 a2 = unpack2(acc[2][p]);
            float2 a3 = unpack2(acc[3][p]);
            y[0][i] = (hi ? a0.y : a0.x) + hv.x;
            y[1][i] = (hi ? a1.y : a1.x) + hv.y;
            y[2][i] = (hi ? a2.y : a2.x) + hv.z;
            y[3][i] = (hi ? a3.y : a3.x) + hv.w;
        }
        float p1[8], p2[8];
        #pragma unroll
        for (int i = 0; i < 8; i++) {
            p1[i] = y[0][i] + y[1][i] + y[2][i] + y[3][i];
            p2[i] = y[0][i] * y[0][i] + y[1][i] * y[1][i]
                  + y[2][i] * y[2][i] + y[3][i] * y[3][i];
        }
        #pragma unroll
        for (int i = 0; i < 8; i++) {
            #pragma unroll
            for (int o = 4; o <= 16; o <<= 1) {
                p1[i] += __shfl_xor_sync(0xFFFFFFFFu, p1[i], o);
                p2[i] += __shfl_xor_sync(0xFFFFFFFFu, p2[i], o);
            }
        }
        if (lane < 4) {
            #pragma unroll
            for (int i = 0; i < 8; i++) {
                s_r1[(lane * 8 + i) * 8 + wrp] = p1[i];
                s_r2[(lane * 8 + i) * 8 + wrp] = p2[i];
            }
        }
        __syncthreads();
        if (tid < TILE) {
            float S1 = 0.0f, S2 = 0.0f;
            #pragma unroll
            for (int i = 0; i < 8; i++) { S1 += s_r1[tid * 8 + i]; S2 += s_r2[tid * 8 + i]; }
            float mu  = S1 * (1.0f / HDIM);
            float var = S2 * (1.0f / HDIM) - mu * mu;
            s_mu[tid] = mu;
            s_rs[tid] = rsqrtf(var + LN_EPS);
        }
        __syncthreads();
        float4 gv = *reinterpret_cast<const float4*>(&lng[f0]);
        float4 bb = *reinterpret_cast<const float4*>(&lnb[f0]);
        #pragma unroll
        for (int i = 0; i < 8; i++) {
            float mu = s_mu[nl + i], rs = s_rs[nl + i];
            float4 o;
            o.x = (y[0][i] - mu) * rs * gv.x + bb.x;
            o.y = (y[1][i] - mu) * rs * gv.y + bb.y;
            o.z = (y[2][i] - mu) * rs * gv.z + bb.z;
            o.w = (y[3][i] - mu) * rs * gv.w + bb.w;
            *reinterpret_cast<float4*>(&out_h[(n0 + nl + i) * HDIM + f0]) = o;
        }
    }
}

// ---------------------------------------------------------------------------
__global__ void xnew_kernel(const float* __restrict__ x, float* __restrict__ out_x) {
    int i = blockIdx.x * blockDim.x + threadIdx.x;
    if (i < NNODE * 3) out_x[i] = x[i] + g_coord[i];
}

// ---------------------------------------------------------------------------
extern "C" void kernel_launch(void* const* d_in, const int* in_sizes, int n_in,
                              void* d_out, int out_size)
{
    const float* h    = (const float*)d_in[0];
    const float* x    = (const float*)d_in[1];
    const void*  ei   = d_in[2];
    const float* e_w1 = (const float*)d_in[3];
    const float* e_b1 = (const float*)d_in[4];
    const float* e_w2 = (const float*)d_in[5];
    const float* e_b2 = (const float*)d_in[6];
    const float* c_w1 = (const float*)d_in[7];
    const float* c_b1 = (const float*)d_in[8];
    const float* c_w2 = (const float*)d_in[9];
    const float* n_w1 = (const float*)d_in[10];
    const float* n_b1 = (const float*)d_in[11];
    const float* n_w2 = (const float*)d_in[12];
    const float* n_b2 = (const float*)d_in[13];
    const float* ln_g = (const float*)d_in[14];
    const float* ln_b = (const float*)d_in[15];
    float* out = (float*)d_out;

    const int prec_smem = (CHUNK * STR) * 4;
    const int node_smem = (CHUNK * STR + 256 * STR + 256 + 256 + 32 + 32) * 4;

    cudaFuncSetAttribute(precomp_kernel, cudaFuncAttributeMaxDynamicSharedMemorySize, prec_smem);
    cudaFuncSetAttribute(node_kernel, cudaFuncAttributeMaxDynamicSharedMemorySize, node_smem);
    cudaFuncSetAttribute(edge_mma_kernel, cudaFuncAttributeMaxDynamicSharedMemorySize, EDGE_SMEM);

    detect_kernel<<<1, 32>>>((const unsigned*)ei);
    zero_kernel<<<512, NTHR>>>();
    transpose_kernel<<<dim3(8, 8, 2), dim3(32, 8)>>>(e_w2, c_w1);
    precomp_kernel<<<dim3(NNODE / TILE, 2), NTHR, prec_smem>>>(h, e_w1);
    edge_mma_kernel<<<NEDGE / ET, ETHR, EDGE_SMEM>>>(x, ei, e_w1, e_b1,
                                                     e_b2, c_b1, c_w2);
    node_kernel<<<NNODE / TILE, NTHR, node_smem>>>(h, n_w1, n_b1, n_w2, n_b2,
                                                   ln_g, ln_b, out);
    xnew_kernel<<<(NNODE * 3 + NTHR - 1) / NTHR, NTHR>>>(x, out + NNODE * HDIM);
}

// round 8
// speedup vs baseline: 4.3724x; 1.1992x over previous
#include <cuda_runtime.h>
#include <cstdint>

// ---------------------------------------------------------------------------
// EGNN layer: N=20000 nodes, E=320000 edges, H=256.
// Round 8: ALL dense GEMMs (precomp P/Q, node MLP, edge MLP) on warp-level
// tf32 mma.sync. Edge kernel unchanged from R7 (validated core).
// ---------------------------------------------------------------------------

#define HDIM    256
#define NNODE   20000
#define NEDGE   320000
#define LN_EPS  1e-5f

#define ET      64           // rows per MMA block
#define ETHR    512          // threads (16 warps: 4M x 4N)

// MMA-kernel smem layout (float offsets)
#define O_M     0            // s_m  [64][260]           = 16640
#define O_B0    16640        // B buf0 [256][36]         =  9216
#define O_B1    25856        // B buf1                   =  9216
#define O_ROW   35072        // 64 int
#define O_COL   35136        // 64 int
#define O_DIST  35200        // 64 f
#define O_DIFF  35264        // 192 f
#define O_RED   35456        // 64*4 f
// node kernel aliases (same footprint region as ROW..RED)
#define O_R1    35072        // 256 f
#define O_R2    35328        // 256 f
#define O_MU    35584        // 64 f
#define O_RS    35648        // 64 f
#define MMA_SMEM ((35712) * 4)

__device__ float g_msg[NNODE * HDIM];
__device__ float g_P[NNODE * HDIM];
__device__ float g_Q[NNODE * HDIM];
__device__ float g_coord[NNODE * 3];
__device__ float g_W2t[HDIM * HDIM];      // W2^T   [n][k] tf32
__device__ float g_C1t[HDIM * HDIM];      // C1^T   [n][k] tf32
__device__ float g_W1at[HDIM * HDIM];     // W1a^T  [n][k] tf32
__device__ float g_W1bt[HDIM * HDIM];     // W1b^T  [n][k] tf32
__device__ float g_NW1t[HDIM * 2 * HDIM]; // NW1^T  [n][k] (ld=512) tf32
__device__ float g_NW2t[HDIM * HDIM];     // NW2^T  [n][k] tf32
__device__ int   g_is64;

__device__ __forceinline__ float silu_f(float v) {
    return v / (1.0f + __expf(-v));
}
__device__ __forceinline__ uint32_t tf32_bits(float x) {
    uint32_t u;
    asm("cvt.rna.tf32.f32 %0, %1;" : "=r"(u) : "f"(x));
    return u;
}
__device__ __forceinline__ float tf32r(float x) {
    return __uint_as_float(tf32_bits(x));
}
__device__ __forceinline__ uint32_t smem_u32(const void* p) {
    uint32_t a;
    asm("{ .reg .u64 t; cvta.to.shared.u64 t, %1; cvt.u32.u64 %0, t; }"
        : "=r"(a) : "l"(p));
    return a;
}

// ---------------------------------------------------------------------------
__global__ void detect_kernel(const unsigned* __restrict__ w) {
    unsigned acc = 0;
    for (int i = threadIdx.x; i < 1024; i += 32) acc |= w[2 * i + 1];
    #pragma unroll
    for (int o = 16; o; o >>= 1) acc |= __shfl_xor_sync(0xFFFFFFFFu, acc, o);
    if (threadIdx.x == 0) g_is64 = (acc == 0) ? 1 : 0;
}

__global__ void zero_kernel() {
    int i = blockIdx.x * blockDim.x + threadIdx.x;
    int stride = gridDim.x * blockDim.x;
    for (int idx = i; idx < NNODE * HDIM; idx += stride) g_msg[idx] = 0.0f;
    for (int idx = i; idx < NNODE * 3;    idx += stride) g_coord[idx] = 0.0f;
}

// transpose + tf32-round all weight matrices into [n][k] device globals.
__global__ void transpose_kernel(const float* __restrict__ W2,
                                 const float* __restrict__ C1,
                                 const float* __restrict__ EW1,
                                 const float* __restrict__ NW1,
                                 const float* __restrict__ NW2) {
    __shared__ float t[32][33];
    const float* src; float* dst; int dld = HDIM; int doff = 0;
    switch (blockIdx.z) {
        case 0: src = W2;                dst = g_W2t;  break;
        case 1: src = C1;                dst = g_C1t;  break;
        case 2: src = EW1;               dst = g_W1at; break;
        case 3: src = EW1 + HDIM * HDIM; dst = g_W1bt; break;
        case 4: src = NW1;               dst = g_NW1t; dld = 2 * HDIM; break;
        default: src = NW1 + HDIM * HDIM; dst = g_NW1t; dld = 2 * HDIM; doff = HDIM; break;
        case 6: src = NW2;               dst = g_NW2t; break;
    }
    int bx = blockIdx.x * 32, by = blockIdx.y * 32;
    int tx = threadIdx.x, ty = threadIdx.y;
    #pragma unroll
    for (int i = 0; i < 32; i += 8)
        t[ty + i][tx] = src[(by + ty + i) * HDIM + bx + tx];
    __syncthreads();
    #pragma unroll
    for (int i = 0; i < 32; i += 8)
        dst[(bx + ty + i) * dld + doff + by + tx] = tf32r(t[tx][ty + i]);
}

// ---------------------------------------------------------------------------
// tf32 warp-MMA GEMM core: D[64 x 256] += s_m[64 x 256k] @ Wt^T.
// Wt global [n][k] row stride ldw (tf32-rounded). 32-k chunks, cp.async x2.
// ---------------------------------------------------------------------------
__device__ __forceinline__ void stage_chunk(const float* __restrict__ Wt,
                                            int ldw, float* sbuf, int c, int tid)
{
    uint32_t dst = smem_u32(sbuf);
    const float* src = Wt + c * 32;
    #pragma unroll
    for (int it = 0; it < 4; it++) {
        int idx = it * ETHR + tid;
        int n  = idx >> 3;
        int k4 = idx & 7;
        uint32_t daddr = dst + (uint32_t)(n * 36 + k4 * 4) * 4u;
        const float* saddr = src + n * ldw + k4 * 4;
        asm volatile("cp.async.cg.shared.global [%0], [%1], 16;"
                     :: "r"(daddr), "l"(saddr));
    }
}

__device__ __forceinline__ void run_gemm(const float* __restrict__ Wt, int ldw,
                                         const float* s_m, float* sb0, float* sb1,
                                         float d[8][4], int m0, int n0b,
                                         int g, int tig, int tid)
{
    stage_chunk(Wt, ldw, sb0, 0, tid);
    asm volatile("cp.async.commit_group;" ::: "memory");
    #pragma unroll 1
    for (int c = 0; c < 8; c++) {
        if (c < 7) {
            stage_chunk(Wt, ldw, (c & 1) ? sb0 : sb1, c + 1, tid);
            asm volatile("cp.async.commit_group;" ::: "memory");
            asm volatile("cp.async.wait_group 1;" ::: "memory");
        } else {
            asm volatile("cp.async.wait_group 0;" ::: "memory");
        }
        __syncthreads();
        const float* sb = (c & 1) ? sb1 : sb0;
        #pragma unroll
        for (int ks = 0; ks < 4; ks++) {
            int kk = c * 32 + ks * 8;
            uint32_t a0 = __float_as_uint(s_m[(m0 + g)     * 260 + kk + tig]);
            uint32_t a1 = __float_as_uint(s_m[(m0 + g + 8) * 260 + kk + tig]);
            uint32_t a2 = __float_as_uint(s_m[(m0 + g)     * 260 + kk + tig + 4]);
            uint32_t a3 = __float_as_uint(s_m[(m0 + g + 8) * 260 + kk + tig + 4]);
            #pragma unroll
            for (int nt = 0; nt < 8; nt++) {
                const float* bp = &sb[(n0b + nt * 8 + g) * 36 + ks * 8 + tig];
                uint32_t b0 = __float_as_uint(bp[0]);
                uint32_t b1 = __float_as_uint(bp[4]);
                asm volatile(
                    "mma.sync.aligned.m16n8k8.row.col.f32.tf32.tf32.f32 "
                    "{%0,%1,%2,%3}, {%4,%5,%6,%7}, {%8,%9}, {%0,%1,%2,%3};"
                    : "+f"(d[nt][0]), "+f"(d[nt][1]), "+f"(d[nt][2]), "+f"(d[nt][3])
                    : "r"(a0), "r"(a1), "r"(a2), "r"(a3), "r"(b0), "r"(b1));
            }
        }
        __syncthreads();
    }
}

// stage 64 rows x 256 cols from src (row stride 256) into s_m as tf32,
// clamping row index to < NNODE.
__device__ __forceinline__ void stage_rows(const float* __restrict__ src,
                                           float* s_m, int n0, int tid)
{
    int f4 = (tid & 63) * 4;
    int rb = tid >> 6;
    #pragma unroll
    for (int j = 0; j < 8; j++) {
        int row = j * 8 + rb;
        int node = n0 + row;
        if (node >= NNODE) node = NNODE - 1;
        float4 v = *reinterpret_cast<const float4*>(&src[node * HDIM + f4]);
        v.x = tf32r(v.x); v.y = tf32r(v.y); v.z = tf32r(v.z); v.w = tf32r(v.w);
        *reinterpret_cast<float4*>(&s_m[row * 260 + f4]) = v;
    }
}

// ---------------------------------------------------------------------------
// Precompute kernel (MMA): P = h @ W1a, Q = h @ W1b. Block = 64 nodes.
// ---------------------------------------------------------------------------
extern __shared__ float smm[];

__global__ __launch_bounds__(ETHR, 1)
void precomp_mma(const float* __restrict__ h)
{
    float* s_m = smm + O_M;
    float* sb0 = smm + O_B0;
    float* sb1 = smm + O_B1;

    const int tid  = threadIdx.x;
    const int lane = tid & 31;
    const int wid  = tid >> 5;
    const int g    = lane >> 2;
    const int tig  = lane & 3;
    const int m0   = (wid >> 2) * 16;
    const int n0b  = (wid & 3) * 64;
    const int n0   = blockIdx.x * ET;

    stage_rows(h, s_m, n0, tid);
    __syncthreads();

    float d[8][4];
    #pragma unroll
    for (int s = 0; s < 2; s++) {
        #pragma unroll
        for (int nt = 0; nt < 8; nt++)
            d[nt][0] = d[nt][1] = d[nt][2] = d[nt][3] = 0.0f;
        run_gemm(s ? g_W1bt : g_W1at, HDIM, s_m, sb0, sb1, d, m0, n0b, g, tig, tid);
        float* out = s ? g_Q : g_P;
        int r0 = n0 + m0 + g, r1 = r0 + 8;
        #pragma unroll
        for (int nt = 0; nt < 8; nt++) {
            int f0 = n0b + nt * 8 + 2 * tig;
            if (r0 < NNODE)
                *reinterpret_cast<float2*>(&out[r0 * HDIM + f0]) =
                    make_float2(d[nt][0], d[nt][1]);
            if (r1 < NNODE)
                *reinterpret_cast<float2*>(&out[r1 * HDIM + f0]) =
                    make_float2(d[nt][2], d[nt][3]);
        }
        __syncthreads();
    }
}

// ---------------------------------------------------------------------------
// Edge kernel (unchanged from R7): one block = 64 edges, tf32 MMA GEMMs.
// ---------------------------------------------------------------------------
__global__ __launch_bounds__(ETHR, 1)
void edge_mma_kernel(const float* __restrict__ x,
                     const void* __restrict__ ei_raw,
                     const float* __restrict__ W1, const float* __restrict__ b1,
                     const float* __restrict__ b2, const float* __restrict__ cb1,
                     const float* __restrict__ C2)
{
    float* s_m   = smm + O_M;
    float* sb0   = smm + O_B0;
    float* sb1   = smm + O_B1;
    int*   s_row = (int*)(smm + O_ROW);
    int*   s_col = (int*)(smm + O_COL);
    float* s_dist = smm + O_DIST;
    float* s_diff = smm + O_DIFF;
    float* s_red  = smm + O_RED;

    const int tid  = threadIdx.x;
    const int lane = tid & 31;
    const int wid  = tid >> 5;
    const int g    = lane >> 2;
    const int tig  = lane & 3;
    const int m0   = (wid >> 2) * 16;
    const int n0b  = (wid & 3) * 64;
    const int e0   = blockIdx.x * ET;

    if (tid < ET) {
        int e = e0 + tid;
        int r, c;
        if (g_is64) {
            const long long* p = (const long long*)ei_raw;
            r = (int)p[e];
            c = (int)p[NEDGE + e];
        } else {
            const int* p = (const int*)ei_raw;
            r = p[e];
            c = p[NEDGE + e];
        }
        s_row[tid] = r;
        s_col[tid] = c;
        float dx = x[r * 3 + 0] - x[c * 3 + 0];
        float dy = x[r * 3 + 1] - x[c * 3 + 1];
        float dz = x[r * 3 + 2] - x[c * 3 + 2];
        s_diff[tid * 3 + 0] = dx;
        s_diff[tid * 3 + 1] = dy;
        s_diff[tid * 3 + 2] = dz;
        s_dist[tid] = dx * dx + dy * dy + dz * dz;
    }
    __syncthreads();

    {
        int f  = tid & 255;
        int eh = tid >> 8;
        float w1d = W1[512 * HDIM + f];
        float b1f = b1[f];
        #pragma unroll 4
        for (int j = 0; j < 32; j++) {
            int e = eh * 32 + j;
            int r = s_row[e], c = s_col[e];
            float v = g_P[r * HDIM + f] + g_Q[c * HDIM + f] + b1f;
            v = fmaf(s_dist[e], w1d, v);
            s_m[e * 260 + f] = tf32r(silu_f(v));
        }
    }
    __syncthreads();

    float d[8][4];

    #pragma unroll
    for (int nt = 0; nt < 8; nt++)
        d[nt][0] = d[nt][1] = d[nt][2] = d[nt][3] = 0.0f;
    run_gemm(g_W2t, HDIM, s_m, sb0, sb1, d, m0, n0b, g, tig, tid);

    #pragma unroll
    for (int nt = 0; nt < 8; nt++) {
        int f0 = n0b + nt * 8 + 2 * tig;
        int er = m0 + g;
        float2 v01 = make_float2(silu_f(d[nt][0] + b2[f0]),
                                 silu_f(d[nt][1] + b2[f0 + 1]));
        float2 v23 = make_float2(silu_f(d[nt][2] + b2[f0]),
                                 silu_f(d[nt][3] + b2[f0 + 1]));
        *reinterpret_cast<float2*>(&s_m[er * 260 + f0])       = v01;
        *reinterpret_cast<float2*>(&s_m[(er + 8) * 260 + f0]) = v23;
    }
    __syncthreads();

    {
        int f4 = (tid & 63) * 4;
        int eh = tid >> 6;
        #pragma unroll
        for (int j = 0; j < 8; j++) {
            int e = eh * 8 + j;
            float4 v = *reinterpret_cast<float4*>(&s_m[e * 260 + f4]);
            atomicAdd(reinterpret_cast<float4*>(&g_msg[s_col[e] * HDIM + f4]), v);
            v.x = tf32r(v.x); v.y = tf32r(v.y); v.z = tf32r(v.z); v.w = tf32r(v.w);
            *reinterpret_cast<float4*>(&s_m[e * 260 + f4]) = v;
        }
    }
    __syncthreads();

    #pragma unroll
    for (int nt = 0; nt < 8; nt++)
        d[nt][0] = d[nt][1] = d[nt][2] = d[nt][3] = 0.0f;
    run_gemm(g_C1t, HDIM, s_m, sb0, sb1, d, m0, n0b, g, tig, tid);

    {
        float cw0 = 0.0f, cw8 = 0.0f;
        #pragma unroll
        for (int nt = 0; nt < 8; nt++) {
            int f0 = n0b + nt * 8 + 2 * tig;
            float c20 = C2[f0], c21 = C2[f0 + 1];
            float bb0 = cb1[f0], bb1 = cb1[f0 + 1];
            cw0 += silu_f(d[nt][0] + bb0) * c20 + silu_f(d[nt][1] + bb1) * c21;
            cw8 += silu_f(d[nt][2] + bb0) * c20 + silu_f(d[nt][3] + bb1) * c21;
        }
        cw0 += __shfl_xor_sync(0xFFFFFFFFu, cw0, 1);
        cw0 += __shfl_xor_sync(0xFFFFFFFFu, cw0, 2);
        cw8 += __shfl_xor_sync(0xFFFFFFFFu, cw8, 1);
        cw8 += __shfl_xor_sync(0xFFFFFFFFu, cw8, 2);
        if (tig == 0) {
            s_red[(m0 + g) * 4 + (wid & 3)]     = cw0;
            s_red[(m0 + g + 8) * 4 + (wid & 3)] = cw8;
        }
    }
    __syncthreads();
    if (tid < ET) {
        float w = s_red[tid * 4] + s_red[tid * 4 + 1]
                + s_red[tid * 4 + 2] + s_red[tid * 4 + 3];
        int c = s_col[tid];
        atomicAdd(&g_coord[c * 3 + 0], w * s_diff[tid * 3 + 0]);
        atomicAdd(&g_coord[c * 3 + 1], w * s_diff[tid * 3 + 1]);
        atomicAdd(&g_coord[c * 3 + 2], w * s_diff[tid * 3 + 2]);
    }
}

// ---------------------------------------------------------------------------
// Node kernel (MMA): block = 64 nodes. GEMM1 (K=512, two staged halves),
// SiLU, GEMM2, residual + LayerNorm epilogue.
// ---------------------------------------------------------------------------
__global__ __launch_bounds__(ETHR, 1)
void node_mma(const float* __restrict__ h,
              const float* __restrict__ nb1, const float* __restrict__ nb2,
              const float* __restrict__ lng, const float* __restrict__ lnb,
              float* __restrict__ out_h)
{
    float* s_m  = smm + O_M;
    float* sb0  = smm + O_B0;
    float* sb1  = smm + O_B1;
    float* s_r1 = smm + O_R1;
    float* s_r2 = smm + O_R2;
    float* s_mu = smm + O_MU;
    float* s_rs = smm + O_RS;

    const int tid  = threadIdx.x;
    const int lane = tid & 31;
    const int wid  = tid >> 5;
    const int g    = lane >> 2;
    const int tig  = lane & 3;
    const int m0   = (wid >> 2) * 16;
    const int n0b  = (wid & 3) * 64;
    const int no   = wid & 3;
    const int n0   = blockIdx.x * ET;

    float d[8][4];

    // ---- GEMM1: u_pre = [h | msg] @ NW1 + nb1  (K = 512, two halves) ----
    #pragma unroll
    for (int nt = 0; nt < 8; nt++) {
        int f0 = n0b + nt * 8 + 2 * tig;
        d[nt][0] = nb1[f0]; d[nt][1] = nb1[f0 + 1];
        d[nt][2] = d[nt][0]; d[nt][3] = d[nt][1];
    }
    stage_rows(h, s_m, n0, tid);
    __syncthreads();
    run_gemm(g_NW1t, 2 * HDIM, s_m, sb0, sb1, d, m0, n0b, g, tig, tid);

    stage_rows(g_msg, s_m, n0, tid);
    __syncthreads();
    run_gemm(g_NW1t + HDIM, 2 * HDIM, s_m, sb0, sb1, d, m0, n0b, g, tig, tid);

    // u = silu(.) -> s_m (tf32) for GEMM2
    #pragma unroll
    for (int nt = 0; nt < 8; nt++) {
        int f0 = n0b + nt * 8 + 2 * tig;
        int r  = m0 + g;
        float2 v01 = make_float2(tf32r(silu_f(d[nt][0])), tf32r(silu_f(d[nt][1])));
        float2 v23 = make_float2(tf32r(silu_f(d[nt][2])), tf32r(silu_f(d[nt][3])));
        *reinterpret_cast<float2*>(&s_m[r * 260 + f0])       = v01;
        *reinterpret_cast<float2*>(&s_m[(r + 8) * 260 + f0]) = v23;
    }
    __syncthreads();

    // ---- GEMM2: y = u @ NW2 + nb2 + h ----
    #pragma unroll
    for (int nt = 0; nt < 8; nt++) {
        int f0 = n0b + nt * 8 + 2 * tig;
        d[nt][0] = nb2[f0]; d[nt][1] = nb2[f0 + 1];
        d[nt][2] = d[nt][0]; d[nt][3] = d[nt][1];
    }
    run_gemm(g_NW2t, HDIM, s_m, sb0, sb1, d, m0, n0b, g, tig, tid);

    const int gr0 = n0 + m0 + g, gr1 = gr0 + 8;
    float s1a = 0.0f, s2a = 0.0f, s1b = 0.0f, s2b = 0.0f;
    #pragma unroll
    for (int nt = 0; nt < 8; nt++) {
        int f0 = n0b + nt * 8 + 2 * tig;
        float2 h0 = (gr0 < NNODE)
            ? *reinterpret_cast<const float2*>(&h[gr0 * HDIM + f0])
            : make_float2(0.0f, 0.0f);
        float2 h1 = (gr1 < NNODE)
            ? *reinterpret_cast<const float2*>(&h[gr1 * HDIM + f0])
            : make_float2(0.0f, 0.0f);
        d[nt][0] += h0.x; d[nt][1] += h0.y;
        d[nt][2] += h1.x; d[nt][3] += h1.y;
        s1a += d[nt][0] + d[nt][1];
        s2a += d[nt][0] * d[nt][0] + d[nt][1] * d[nt][1];
        s1b += d[nt][2] + d[nt][3];
        s2b += d[nt][2] * d[nt][2] + d[nt][3] * d[nt][3];
    }
    // reduce over tig quad (covers this warp's 64 cols)
    #pragma unroll
    for (int o = 1; o <= 2; o <<= 1) {
        s1a += __shfl_xor_sync(0xFFFFFFFFu, s1a, o);
        s2a += __shfl_xor_sync(0xFFFFFFFFu, s2a, o);
        s1b += __shfl_xor_sync(0xFFFFFFFFu, s1b, o);
        s2b += __shfl_xor_sync(0xFFFFFFFFu, s2b, o);
    }
    if (tig == 0) {
        s_r1[(m0 + g) * 4 + no]     = s1a;
        s_r2[(m0 + g) * 4 + no]     = s2a;
        s_r1[(m0 + g + 8) * 4 + no] = s1b;
        s_r2[(m0 + g + 8) * 4 + no] = s2b;
    }
    __syncthreads();
    if (tid < ET) {
        float S1 = s_r1[tid * 4] + s_r1[tid * 4 + 1]
                 + s_r1[tid * 4 + 2] + s_r1[tid * 4 + 3];
        float S2 = s_r2[tid * 4] + s_r2[tid * 4 + 1]
                 + s_r2[tid * 4 + 2] + s_r2[tid * 4 + 3];
        float mu  = S1 * (1.0f / HDIM);
        float var = S2 * (1.0f / HDIM) - mu * mu;
        s_mu[tid] = mu;
        s_rs[tid] = rsqrtf(var + LN_EPS);
    }
    __syncthreads();
    float mu0 = s_mu[m0 + g],     rs0 = s_rs[m0 + g];
    float mu1 = s_mu[m0 + g + 8], rs1 = s_rs[m0 + g + 8];
    #pragma unroll
    for (int nt = 0; nt < 8; nt++) {
        int f0 = n0b + nt * 8 + 2 * tig;
        float g0 = lng[f0], g1 = lng[f0 + 1];
        float b0 = lnb[f0], b1v = lnb[f0 + 1];
        if (gr0 < NNODE)
            *reinterpret_cast<float2*>(&out_h[gr0 * HDIM + f0]) =
                make_float2((d[nt][0] - mu0) * rs0 * g0 + b0,
                            (d[nt][1] - mu0) * rs0 * g1 + b1v);
        if (gr1 < NNODE)
            *reinterpret_cast<float2*>(&out_h[gr1 * HDIM + f0]) =
                make_float2((d[nt][2] - mu1) * rs1 * g0 + b0,
                            (d[nt][3] - mu1) * rs1 * g1 + b1v);
    }
}

// ---------------------------------------------------------------------------
__global__ void xnew_kernel(const float* __restrict__ x, float* __restrict__ out_x) {
    int i = blockIdx.x * blockDim.x + threadIdx.x;
    if (i < NNODE * 3) out_x[i] = x[i] + g_coord[i];
}

// ---------------------------------------------------------------------------
extern "C" void kernel_launch(void* const* d_in, const int* in_sizes, int n_in,
                              void* d_out, int out_size)
{
    const float* h    = (const float*)d_in[0];
    const float* x    = (const float*)d_in[1];
    const void*  ei   = d_in[2];
    const float* e_w1 = (const float*)d_in[3];
    const float* e_b1 = (const float*)d_in[4];
    const float* e_w2 = (const float*)d_in[5];
    const float* e_b2 = (const float*)d_in[6];
    const float* c_w1 = (const float*)d_in[7];
    const float* c_b1 = (const float*)d_in[8];
    const float* c_w2 = (const float*)d_in[9];
    const float* n_w1 = (const float*)d_in[10];
    const float* n_b1 = (const float*)d_in[11];
    const float* n_w2 = (const float*)d_in[12];
    const float* n_b2 = (const float*)d_in[13];
    const float* ln_g = (const float*)d_in[14];
    const float* ln_b = (const float*)d_in[15];
    float* out = (float*)d_out;

    cudaFuncSetAttribute(precomp_mma,     cudaFuncAttributeMaxDynamicSharedMemorySize, MMA_SMEM);
    cudaFuncSetAttribute(edge_mma_kernel, cudaFuncAttributeMaxDynamicSharedMemorySize, MMA_SMEM);
    cudaFuncSetAttribute(node_mma,        cudaFuncAttributeMaxDynamicSharedMemorySize, MMA_SMEM);

    const int nblk = (NNODE + ET - 1) / ET;

    detect_kernel<<<1, 32>>>((const unsigned*)ei);
    zero_kernel<<<512, 256>>>();
    transpose_kernel<<<dim3(8, 8, 7), dim3(32, 8)>>>(e_w2, c_w1, e_w1, n_w1, n_w2);
    precomp_mma<<<nblk, ETHR, MMA_SMEM>>>(h);
    edge_mma_kernel<<<NEDGE / ET, ETHR, MMA_SMEM>>>(x, ei, e_w1, e_b1,
                                                    e_b2, c_b1, c_w2);
    node_mma<<<nblk, ETHR, MMA_SMEM>>>(h, n_b1, n_b2, ln_g, ln_b, out);
    xnew_kernel<<<(NNODE * 3 + 255) / 256, 256>>>(x, out + NNODE * HDIM);
}

// round 9
// speedup vs baseline: 6.2658x; 1.4330x over previous
#include <cuda_runtime.h>
#include <cstdint>

// ---------------------------------------------------------------------------
// EGNN layer: N=20000 nodes, E=320000 edges, H=256.
// Round 9: barrier-free tf32 MMA GEMM core. B operands in fragment-packed
// global layout, loaded per-lane via LDG.NC.64 (no smem staging, no inner
// barriers). smem 143->69KB + launch_bounds(512,2) -> 2 CTAs/SM.
// ---------------------------------------------------------------------------

#define HDIM    256
#define NNODE   20000
#define NEDGE   320000
#define LN_EPS  1e-5f

#define ET      64           // rows per MMA block
#define ETHR    512          // threads (16 warps: 4M x 4N)

// MMA-kernel smem layout (float offsets)
#define O_M     0            // s_m  [64][260] = 16640
#define O_ROW   16640        // 64 int
#define O_COL   16704        // 64 int
#define O_DIST  16768        // 64 f
#define O_DIFF  16832        // 192 f
#define O_RED   17024        // 64*4 f
// node kernel aliases (same region as ROW..RED)
#define O_R1    16640        // 256 f
#define O_R2    16896        // 256 f
#define O_MU    17152        // 64 f
#define O_RS    17216        // 64 f
#define MMA_SMEM (17280 * 4)

__device__ float g_msg[NNODE * HDIM];
__device__ float g_P[NNODE * HDIM];
__device__ float g_Q[NNODE * HDIM];
__device__ float g_coord[NNODE * 3];
// fragment-packed tf32 weights: tile(nb,kb) = 64 floats, lane-ordered
__device__ float g_W2t[HDIM * HDIM];
__device__ float g_C1t[HDIM * HDIM];
__device__ float g_W1at[HDIM * HDIM];
__device__ float g_W1bt[HDIM * HDIM];
__device__ float g_NW1t[HDIM * 2 * HDIM];   // K = 512 (KB8 = 64)
__device__ float g_NW2t[HDIM * HDIM];
__device__ int   g_is64;

__device__ __forceinline__ float silu_f(float v) {
    return v / (1.0f + __expf(-v));
}
__device__ __forceinline__ uint32_t tf32_bits(float x) {
    uint32_t u;
    asm("cvt.rna.tf32.f32 %0, %1;" : "=r"(u) : "f"(x));
    return u;
}
__device__ __forceinline__ float tf32r(float x) {
    return __uint_as_float(tf32_bits(x));
}

// ---------------------------------------------------------------------------
__global__ void detect_kernel(const unsigned* __restrict__ w) {
    unsigned acc = 0;
    for (int i = threadIdx.x; i < 1024; i += 32) acc |= w[2 * i + 1];
    #pragma unroll
    for (int o = 16; o; o >>= 1) acc |= __shfl_xor_sync(0xFFFFFFFFu, acc, o);
    if (threadIdx.x == 0) g_is64 = (acc == 0) ? 1 : 0;
}

__global__ void zero_kernel() {
    int i = blockIdx.x * blockDim.x + threadIdx.x;
    int stride = gridDim.x * blockDim.x;
    for (int idx = i; idx < NNODE * HDIM; idx += stride) g_msg[idx] = 0.0f;
    for (int idx = i; idx < NNODE * 3;    idx += stride) g_coord[idx] = 0.0f;
}

// transpose + tf32-round + fragment-pack all weight matrices.
// Element (n, k) of W^T goes to tile (n>>3, k>>3), offset
// ((n&7)*4 + (k&3))*2 + ((k>>2)&1)  -- one LDG.64 per lane per (ks,nt).
__global__ void transpose_kernel(const float* __restrict__ W2,
                                 const float* __restrict__ C1,
                                 const float* __restrict__ EW1,
                                 const float* __restrict__ NW1,
                                 const float* __restrict__ NW2) {
    __shared__ float t[32][33];
    const float* src; float* dst; int kdim = HDIM; int doff = 0;
    switch (blockIdx.z) {
        case 0: src = W2;                dst = g_W2t;  break;
        case 1: src = C1;                dst = g_C1t;  break;
        case 2: src = EW1;               dst = g_W1at; break;
        case 3: src = EW1 + HDIM * HDIM; dst = g_W1bt; break;
        case 4: src = NW1;               dst = g_NW1t; kdim = 2 * HDIM; break;
        default: src = NW1 + HDIM * HDIM; dst = g_NW1t; kdim = 2 * HDIM; doff = HDIM; break;
        case 6: src = NW2;               dst = g_NW2t; break;
    }
    int bx = blockIdx.x * 32, by = blockIdx.y * 32;
    int tx = threadIdx.x, ty = threadIdx.y;
    #pragma unroll
    for (int i = 0; i < 32; i += 8)
        t[ty + i][tx] = src[(by + ty + i) * HDIM + bx + tx];
    __syncthreads();
    int KB8 = kdim >> 3;
    #pragma unroll
    for (int i = 0; i < 32; i += 8) {
        int n = bx + ty + i;
        int k = doff + by + tx;
        int off = ((n >> 3) * KB8 + (k >> 3)) * 64
                + ((n & 7) * 4 + (k & 3)) * 2 + ((k >> 2) & 1);
        dst[off] = tf32r(t[tx][ty + i]);
    }
}

// ---------------------------------------------------------------------------
// Barrier-free tf32 warp-MMA GEMM: D[64 x 256] += s_m[64 x 256k] @ W^T.
// Wp: fragment-packed weights; KB8 = K/8 tiles per n-row; kb0 = k-block base.
// Ends with one __syncthreads (all warps done reading s_m).
// ---------------------------------------------------------------------------
__device__ __forceinline__ void run_gemm(const float* __restrict__ Wp,
                                         int KB8, int kb0,
                                         const float* s_m, float d[8][4],
                                         int m0, int nb0,
                                         int g, int tig, int lane)
{
    #pragma unroll 1
    for (int c = 0; c < 8; c++) {
        #pragma unroll
        for (int ks = 0; ks < 4; ks++) {
            int kk = c * 32 + ks * 8;
            int kb = kb0 + (kk >> 3);
            uint32_t a0 = __float_as_uint(s_m[(m0 + g)     * 260 + kk + tig]);
            uint32_t a1 = __float_as_uint(s_m[(m0 + g + 8) * 260 + kk + tig]);
            uint32_t a2 = __float_as_uint(s_m[(m0 + g)     * 260 + kk + tig + 4]);
            uint32_t a3 = __float_as_uint(s_m[(m0 + g + 8) * 260 + kk + tig + 4]);
            #pragma unroll
            for (int nt = 0; nt < 8; nt++) {
                float2 bv = __ldg(reinterpret_cast<const float2*>(
                                      Wp + ((nb0 + nt) * KB8 + kb) * 64) + lane);
                uint32_t b0 = __float_as_uint(bv.x);
                uint32_t b1 = __float_as_uint(bv.y);
                asm volatile(
                    "mma.sync.aligned.m16n8k8.row.col.f32.tf32.tf32.f32 "
                    "{%0,%1,%2,%3}, {%4,%5,%6,%7}, {%8,%9}, {%0,%1,%2,%3};"
                    : "+f"(d[nt][0]), "+f"(d[nt][1]), "+f"(d[nt][2]), "+f"(d[nt][3])
                    : "r"(a0), "r"(a1), "r"(a2), "r"(a3), "r"(b0), "r"(b1));
            }
        }
    }
    __syncthreads();
}

// stage 64 rows x 256 cols from src (row stride 256) into s_m as tf32.
__device__ __forceinline__ void stage_rows(const float* __restrict__ src,
                                           float* s_m, int n0, int tid)
{
    int f4 = (tid & 63) * 4;
    int rb = tid >> 6;
    #pragma unroll
    for (int j = 0; j < 8; j++) {
        int row = j * 8 + rb;
        int node = n0 + row;
        if (node >= NNODE) node = NNODE - 1;
        float4 v = *reinterpret_cast<const float4*>(&src[node * HDIM + f4]);
        v.x = tf32r(v.x); v.y = tf32r(v.y); v.z = tf32r(v.z); v.w = tf32r(v.w);
        *reinterpret_cast<float4*>(&s_m[row * 260 + f4]) = v;
    }
}

// ---------------------------------------------------------------------------
// Precompute kernel (MMA): P = h @ W1a, Q = h @ W1b. Block = 64 nodes.
// ---------------------------------------------------------------------------
extern __shared__ float smm[];

__global__ __launch_bounds__(ETHR, 2)
void precomp_mma(const float* __restrict__ h)
{
    float* s_m = smm + O_M;

    const int tid  = threadIdx.x;
    const int lane = tid & 31;
    const int wid  = tid >> 5;
    const int g    = lane >> 2;
    const int tig  = lane & 3;
    const int m0   = (wid >> 2) * 16;
    const int nb0  = (wid & 3) * 8;
    const int n0b  = nb0 * 8;
    const int n0   = blockIdx.x * ET;

    stage_rows(h, s_m, n0, tid);
    __syncthreads();

    float d[8][4];
    #pragma unroll
    for (int s = 0; s < 2; s++) {
        #pragma unroll
        for (int nt = 0; nt < 8; nt++)
            d[nt][0] = d[nt][1] = d[nt][2] = d[nt][3] = 0.0f;
        run_gemm(s ? g_W1bt : g_W1at, 32, 0, s_m, d, m0, nb0, g, tig, lane);
        float* out = s ? g_Q : g_P;
        int r0 = n0 + m0 + g, r1 = r0 + 8;
        #pragma unroll
        for (int nt = 0; nt < 8; nt++) {
            int f0 = n0b + nt * 8 + 2 * tig;
            if (r0 < NNODE)
                *reinterpret_cast<float2*>(&out[r0 * HDIM + f0]) =
                    make_float2(d[nt][0], d[nt][1]);
            if (r1 < NNODE)
                *reinterpret_cast<float2*>(&out[r1 * HDIM + f0]) =
                    make_float2(d[nt][2], d[nt][3]);
        }
    }
}

// ---------------------------------------------------------------------------
// Edge kernel: one block = 64 edges, tf32 MMA GEMMs.
// ---------------------------------------------------------------------------
__global__ __launch_bounds__(ETHR, 2)
void edge_mma_kernel(const float* __restrict__ x,
                     const void* __restrict__ ei_raw,
                     const float* __restrict__ W1, const float* __restrict__ b1,
                     const float* __restrict__ b2, const float* __restrict__ cb1,
                     const float* __restrict__ C2)
{
    float* s_m   = smm + O_M;
    int*   s_row = (int*)(smm + O_ROW);
    int*   s_col = (int*)(smm + O_COL);
    float* s_dist = smm + O_DIST;
    float* s_diff = smm + O_DIFF;
    float* s_red  = smm + O_RED;

    const int tid  = threadIdx.x;
    const int lane = tid & 31;
    const int wid  = tid >> 5;
    const int g    = lane >> 2;
    const int tig  = lane & 3;
    const int m0   = (wid >> 2) * 16;
    const int nb0  = (wid & 3) * 8;
    const int n0b  = nb0 * 8;
    const int e0   = blockIdx.x * ET;

    if (tid < ET) {
        int e = e0 + tid;
        int r, c;
        if (g_is64) {
            const long long* p = (const long long*)ei_raw;
            r = (int)p[e];
            c = (int)p[NEDGE + e];
        } else {
            const int* p = (const int*)ei_raw;
            r = p[e];
            c = p[NEDGE + e];
        }
        s_row[tid] = r;
        s_col[tid] = c;
        float dx = x[r * 3 + 0] - x[c * 3 + 0];
        float dy = x[r * 3 + 1] - x[c * 3 + 1];
        float dz = x[r * 3 + 2] - x[c * 3 + 2];
        s_diff[tid * 3 + 0] = dx;
        s_diff[tid * 3 + 1] = dy;
        s_diff[tid * 3 + 2] = dz;
        s_dist[tid] = dx * dx + dy * dy + dz * dz;
    }
    __syncthreads();

    // ---- phase B: m = silu(P[row]+Q[col]+dist*w1d+b1) -> s_m (tf32) ----
    {
        int f  = tid & 255;
        int eh = tid >> 8;
        float w1d = W1[512 * HDIM + f];
        float b1f = b1[f];
        #pragma unroll 4
        for (int j = 0; j < 32; j++) {
            int e = eh * 32 + j;
            int r = s_row[e], c = s_col[e];
            float v = g_P[r * HDIM + f] + g_Q[c * HDIM + f] + b1f;
            v = fmaf(s_dist[e], w1d, v);
            s_m[e * 260 + f] = tf32r(silu_f(v));
        }
    }
    __syncthreads();

    float d[8][4];

    // ---- GEMM1: D = m @ W2 ----
    #pragma unroll
    for (int nt = 0; nt < 8; nt++)
        d[nt][0] = d[nt][1] = d[nt][2] = d[nt][3] = 0.0f;
    run_gemm(g_W2t, 32, 0, s_m, d, m0, nb0, g, tig, lane);

    // ---- readback1: m_ij = silu(D + b2) -> s_m (exact fp32) ----
    #pragma unroll
    for (int nt = 0; nt < 8; nt++) {
        int f0 = n0b + nt * 8 + 2 * tig;
        int er = m0 + g;
        float2 v01 = make_float2(silu_f(d[nt][0] + b2[f0]),
                                 silu_f(d[nt][1] + b2[f0 + 1]));
        float2 v23 = make_float2(silu_f(d[nt][2] + b2[f0]),
                                 silu_f(d[nt][3] + b2[f0 + 1]));
        *reinterpret_cast<float2*>(&s_m[er * 260 + f0])       = v01;
        *reinterpret_cast<float2*>(&s_m[(er + 8) * 260 + f0]) = v23;
    }
    __syncthreads();

    // ---- scatter exact m_ij; convert s_m to tf32 for GEMM2 ----
    {
        int f4 = (tid & 63) * 4;
        int eh = tid >> 6;
        #pragma unroll
        for (int j = 0; j < 8; j++) {
            int e = eh * 8 + j;
            float4 v = *reinterpret_cast<float4*>(&s_m[e * 260 + f4]);
            atomicAdd(reinterpret_cast<float4*>(&g_msg[s_col[e] * HDIM + f4]), v);
            v.x = tf32r(v.x); v.y = tf32r(v.y); v.z = tf32r(v.z); v.w = tf32r(v.w);
            *reinterpret_cast<float4*>(&s_m[e * 260 + f4]) = v;
        }
    }
    __syncthreads();

    // ---- GEMM2: D = m_ij @ C1 ----
    #pragma unroll
    for (int nt = 0; nt < 8; nt++)
        d[nt][0] = d[nt][1] = d[nt][2] = d[nt][3] = 0.0f;
    run_gemm(g_C1t, 32, 0, s_m, d, m0, nb0, g, tig, lane);

    // ---- readback2: coord_weight = sum_f silu(D + cb1) * C2 ----
    {
        float cw0 = 0.0f, cw8 = 0.0f;
        #pragma unroll
        for (int nt = 0; nt < 8; nt++) {
            int f0 = n0b + nt * 8 + 2 * tig;
            float c20 = C2[f0], c21 = C2[f0 + 1];
            float bb0 = cb1[f0], bb1 = cb1[f0 + 1];
            cw0 += silu_f(d[nt][0] + bb0) * c20 + silu_f(d[nt][1] + bb1) * c21;
            cw8 += silu_f(d[nt][2] + bb0) * c20 + silu_f(d[nt][3] + bb1) * c21;
        }
        cw0 += __shfl_xor_sync(0xFFFFFFFFu, cw0, 1);
        cw0 += __shfl_xor_sync(0xFFFFFFFFu, cw0, 2);
        cw8 += __shfl_xor_sync(0xFFFFFFFFu, cw8, 1);
        cw8 += __shfl_xor_sync(0xFFFFFFFFu, cw8, 2);
        if (tig == 0) {
            s_red[(m0 + g) * 4 + (wid & 3)]     = cw0;
            s_red[(m0 + g + 8) * 4 + (wid & 3)] = cw8;
        }
    }
    __syncthreads();
    if (tid < ET) {
        float w = s_red[tid * 4] + s_red[tid * 4 + 1]
                + s_red[tid * 4 + 2] + s_red[tid * 4 + 3];
        int c = s_col[tid];
        atomicAdd(&g_coord[c * 3 + 0], w * s_diff[tid * 3 + 0]);
        atomicAdd(&g_coord[c * 3 + 1], w * s_diff[tid * 3 + 1]);
        atomicAdd(&g_coord[c * 3 + 2], w * s_diff[tid * 3 + 2]);
    }
}

// ---------------------------------------------------------------------------
// Node kernel (MMA): block = 64 nodes. GEMM1 (K=512, two halves), SiLU,
// GEMM2, residual + LayerNorm epilogue.
// ---------------------------------------------------------------------------
__global__ __launch_bounds__(ETHR, 2)
void node_mma(const float* __restrict__ h,
              const float* __restrict__ nb1, const float* __restrict__ nb2,
              const float* __restrict__ lng, const float* __restrict__ lnb,
              float* __restrict__ out_h)
{
    float* s_m  = smm + O_M;
    float* s_r1 = smm + O_R1;
    float* s_r2 = smm + O_R2;
    float* s_mu = smm + O_MU;
    float* s_rs = smm + O_RS;

    const int tid  = threadIdx.x;
    const int lane = tid & 31;
    const int wid  = tid >> 5;
    const int g    = lane >> 2;
    const int tig  = lane & 3;
    const int m0   = (wid >> 2) * 16;
    const int nb0  = (wid & 3) * 8;
    const int n0b  = nb0 * 8;
    const int no   = wid & 3;
    const int n0   = blockIdx.x * ET;

    float d[8][4];

    // ---- GEMM1: u_pre = [h | msg] @ NW1 + nb1  (K = 512, two halves) ----
    #pragma unroll
    for (int nt = 0; nt < 8; nt++) {
        int f0 = n0b + nt * 8 + 2 * tig;
        d[nt][0] = nb1[f0]; d[nt][1] = nb1[f0 + 1];
        d[nt][2] = d[nt][0]; d[nt][3] = d[nt][1];
    }
    stage_rows(h, s_m, n0, tid);
    __syncthreads();
    run_gemm(g_NW1t, 64, 0, s_m, d, m0, nb0, g, tig, lane);

    stage_rows(g_msg, s_m, n0, tid);
    __syncthreads();
    run_gemm(g_NW1t, 64, 32, s_m, d, m0, nb0, g, tig, lane);

    // u = silu(.) -> s_m (tf32) for GEMM2
    #pragma unroll
    for (int nt = 0; nt < 8; nt++) {
        int f0 = n0b + nt * 8 + 2 * tig;
        int r  = m0 + g;
        float2 v01 = make_float2(tf32r(silu_f(d[nt][0])), tf32r(silu_f(d[nt][1])));
        float2 v23 = make_float2(tf32r(silu_f(d[nt][2])), tf32r(silu_f(d[nt][3])));
        *reinterpret_cast<float2*>(&s_m[r * 260 + f0])       = v01;
        *reinterpret_cast<float2*>(&s_m[(r + 8) * 260 + f0]) = v23;
    }
    __syncthreads();

    // ---- GEMM2: y = u @ NW2 + nb2 + h ----
    #pragma unroll
    for (int nt = 0; nt < 8; nt++) {
        int f0 = n0b + nt * 8 + 2 * tig;
        d[nt][0] = nb2[f0]; d[nt][1] = nb2[f0 + 1];
        d[nt][2] = d[nt][0]; d[nt][3] = d[nt][1];
    }
    run_gemm(g_NW2t, 32, 0, s_m, d, m0, nb0, g, tig, lane);

    const int gr0 = n0 + m0 + g, gr1 = gr0 + 8;
    float s1a = 0.0f, s2a = 0.0f, s1b = 0.0f, s2b = 0.0f;
    #pragma unroll
    for (int nt = 0; nt < 8; nt++) {
        int f0 = n0b + nt * 8 + 2 * tig;
        float2 h0 = (gr0 < NNODE)
            ? *reinterpret_cast<const float2*>(&h[gr0 * HDIM + f0])
            : make_float2(0.0f, 0.0f);
        float2 h1 = (gr1 < NNODE)
            ? *reinterpret_cast<const float2*>(&h[gr1 * HDIM + f0])
            : make_float2(0.0f, 0.0f);
        d[nt][0] += h0.x; d[nt][1] += h0.y;
        d[nt][2] += h1.x; d[nt][3] += h1.y;
        s1a += d[nt][0] + d[nt][1];
        s2a += d[nt][0] * d[nt][0] + d[nt][1] * d[nt][1];
        s1b += d[nt][2] + d[nt][3];
        s2b += d[nt][2] * d[nt][2] + d[nt][3] * d[nt][3];
    }
    #pragma unroll
    for (int o = 1; o <= 2; o <<= 1) {
        s1a += __shfl_xor_sync(0xFFFFFFFFu, s1a, o);
        s2a += __shfl_xor_sync(0xFFFFFFFFu, s2a, o);
        s1b += __shfl_xor_sync(0xFFFFFFFFu, s1b, o);
        s2b += __shfl_xor_sync(0xFFFFFFFFu, s2b, o);
    }
    if (tig == 0) {
        s_r1[(m0 + g) * 4 + no]     = s1a;
        s_r2[(m0 + g) * 4 + no]     = s2a;
        s_r1[(m0 + g + 8) * 4 + no] = s1b;
        s_r2[(m0 + g + 8) * 4 + no] = s2b;
    }
    __syncthreads();
    if (tid < ET) {
        float S1 = s_r1[tid * 4] + s_r1[tid * 4 + 1]
                 + s_r1[tid * 4 + 2] + s_r1[tid * 4 + 3];
        float S2 = s_r2[tid * 4] + s_r2[tid * 4 + 1]
                 + s_r2[tid * 4 + 2] + s_r2[tid * 4 + 3];
        float mu  = S1 * (1.0f / HDIM);
        float var = S2 * (1.0f / HDIM) - mu * mu;
        s_mu[tid] = mu;
        s_rs[tid] = rsqrtf(var + LN_EPS);
    }
    __syncthreads();
    float mu0 = s_mu[m0 + g],     rs0 = s_rs[m0 + g];
    float mu1 = s_mu[m0 + g + 8], rs1 = s_rs[m0 + g + 8];
    #pragma unroll
    for (int nt = 0; nt < 8; nt++) {
        int f0 = n0b + nt * 8 + 2 * tig;
        float g0 = lng[f0], g1 = lng[f0 + 1];
        float b0 = lnb[f0], b1v = lnb[f0 + 1];
        if (gr0 < NNODE)
            *reinterpret_cast<float2*>(&out_h[gr0 * HDIM + f0]) =
                make_float2((d[nt][0] - mu0) * rs0 * g0 + b0,
                            (d[nt][1] - mu0) * rs0 * g1 + b1v);
        if (gr1 < NNODE)
            *reinterpret_cast<float2*>(&out_h[gr1 * HDIM + f0]) =
                make_float2((d[nt][2] - mu1) * rs1 * g0 + b0,
                            (d[nt][3] - mu1) * rs1 * g1 + b1v);
    }
}

// ---------------------------------------------------------------------------
__global__ void xnew_kernel(const float* __restrict__ x, float* __restrict__ out_x) {
    int i = blockIdx.x * blockDim.x + threadIdx.x;
    if (i < NNODE * 3) out_x[i] = x[i] + g_coord[i];
}

// ---------------------------------------------------------------------------
extern "C" void kernel_launch(void* const* d_in, const int* in_sizes, int n_in,
                              void* d_out, int out_size)
{
    const float* h    = (const float*)d_in[0];
    const float* x    = (const float*)d_in[1];
    const void*  ei   = d_in[2];
    const float* e_w1 = (const float*)d_in[3];
    const float* e_b1 = (const float*)d_in[4];
    const float* e_w2 = (const float*)d_in[5];
    const float* e_b2 = (const float*)d_in[6];
    const float* c_w1 = (const float*)d_in[7];
    const float* c_b1 = (const float*)d_in[8];
    const float* c_w2 = (const float*)d_in[9];
    const float* n_w1 = (const float*)d_in[10];
    const float* n_b1 = (const float*)d_in[11];
    const float* n_w2 = (const float*)d_in[12];
    const float* n_b2 = (const float*)d_in[13];
    const float* ln_g = (const float*)d_in[14];
    const float* ln_b = (const float*)d_in[15];
    float* out = (float*)d_out;

    cudaFuncSetAttribute(precomp_mma,     cudaFuncAttributeMaxDynamicSharedMemorySize, MMA_SMEM);
    cudaFuncSetAttribute(edge_mma_kernel, cudaFuncAttributeMaxDynamicSharedMemorySize, MMA_SMEM);
    cudaFuncSetAttribute(node_mma,        cudaFuncAttributeMaxDynamicSharedMemorySize, MMA_SMEM);

    const int nblk = (NNODE + ET - 1) / ET;

    detect_kernel<<<1, 32>>>((const unsigned*)ei);
    zero_kernel<<<512, 256>>>();
    transpose_kernel<<<dim3(8, 8, 7), dim3(32, 8)>>>(e_w2, c_w1, e_w1, n_w1, n_w2);
    precomp_mma<<<nblk, ETHR, MMA_SMEM>>>(h);
    edge_mma_kernel<<<NEDGE / ET, ETHR, MMA_SMEM>>>(x, ei, e_w1, e_b1,
                                                    e_b2, c_b1, c_w2);
    node_mma<<<nblk, ETHR, MMA_SMEM>>>(h, n_b1, n_b2, ln_g, ln_b, out);
    xnew_kernel<<<(NNODE * 3 + 255) / 256, 256>>>(x, out + NNODE * HDIM);
}

// round 10
// speedup vs baseline: 7.9512x; 1.2690x over previous
#include <cuda_runtime.h>
#include <cstdint>

// ---------------------------------------------------------------------------
// EGNN layer: N=20000 nodes, E=320000 edges, H=256.
// Round 10: warp grid 4Mx4N -> 2Mx8N (warp tile 32r x 32c). Halves B-operand
// LDG traffic (duplication 4x -> 2x); A comes from conflict-free LDS.
// ---------------------------------------------------------------------------

#define HDIM    256
#define NNODE   20000
#define NEDGE   320000
#define LN_EPS  1e-5f

#define ET      64           // rows per MMA block
#define ETHR    512          // threads (16 warps: 2M x 8N)

// MMA-kernel smem layout (float offsets)
#define O_M     0            // s_m  [64][260] = 16640
#define O_ROW   16640        // 64 int
#define O_COL   16704        // 64 int
#define O_DIST  16768        // 64 f
#define O_DIFF  16832        // 192 f
#define O_RED   17024        // 64*8 f = 512
// node kernel aliases (same region as ROW..RED)
#define O_R1    16640        // 512 f
#define O_R2    17152        // 512 f
#define O_MU    17664        // 64 f
#define O_RS    17728        // 64 f
#define MMA_SMEM (17792 * 4)

__device__ float g_msg[NNODE * HDIM];
__device__ float g_P[NNODE * HDIM];
__device__ float g_Q[NNODE * HDIM];
__device__ float g_coord[NNODE * 3];
// fragment-packed tf32 weights: tile(nb,kb) = 64 floats, lane-ordered
__device__ float g_W2t[HDIM * HDIM];
__device__ float g_C1t[HDIM * HDIM];
__device__ float g_W1at[HDIM * HDIM];
__device__ float g_W1bt[HDIM * HDIM];
__device__ float g_NW1t[HDIM * 2 * HDIM];   // K = 512 (KB8 = 64)
__device__ float g_NW2t[HDIM * HDIM];
__device__ int   g_is64;

__device__ __forceinline__ float silu_f(float v) {
    return v / (1.0f + __expf(-v));
}
__device__ __forceinline__ uint32_t tf32_bits(float x) {
    uint32_t u;
    asm("cvt.rna.tf32.f32 %0, %1;" : "=r"(u) : "f"(x));
    return u;
}
__device__ __forceinline__ float tf32r(float x) {
    return __uint_as_float(tf32_bits(x));
}

// ---------------------------------------------------------------------------
__global__ void detect_kernel(const unsigned* __restrict__ w) {
    unsigned acc = 0;
    for (int i = threadIdx.x; i < 1024; i += 32) acc |= w[2 * i + 1];
    #pragma unroll
    for (int o = 16; o; o >>= 1) acc |= __shfl_xor_sync(0xFFFFFFFFu, acc, o);
    if (threadIdx.x == 0) g_is64 = (acc == 0) ? 1 : 0;
}

__global__ void zero_kernel() {
    int i = blockIdx.x * blockDim.x + threadIdx.x;
    int stride = gridDim.x * blockDim.x;
    for (int idx = i; idx < NNODE * HDIM; idx += stride) g_msg[idx] = 0.0f;
    for (int idx = i; idx < NNODE * 3;    idx += stride) g_coord[idx] = 0.0f;
}

// transpose + tf32-round + fragment-pack all weight matrices.
__global__ void transpose_kernel(const float* __restrict__ W2,
                                 const float* __restrict__ C1,
                                 const float* __restrict__ EW1,
                                 const float* __restrict__ NW1,
                                 const float* __restrict__ NW2) {
    __shared__ float t[32][33];
    const float* src; float* dst; int kdim = HDIM; int doff = 0;
    switch (blockIdx.z) {
        case 0: src = W2;                dst = g_W2t;  break;
        case 1: src = C1;                dst = g_C1t;  break;
        case 2: src = EW1;               dst = g_W1at; break;
        case 3: src = EW1 + HDIM * HDIM; dst = g_W1bt; break;
        case 4: src = NW1;               dst = g_NW1t; kdim = 2 * HDIM; break;
        default: src = NW1 + HDIM * HDIM; dst = g_NW1t; kdim = 2 * HDIM; doff = HDIM; break;
        case 6: src = NW2;               dst = g_NW2t; break;
    }
    int bx = blockIdx.x * 32, by = blockIdx.y * 32;
    int tx = threadIdx.x, ty = threadIdx.y;
    #pragma unroll
    for (int i = 0; i < 32; i += 8)
        t[ty + i][tx] = src[(by + ty + i) * HDIM + bx + tx];
    __syncthreads();
    int KB8 = kdim >> 3;
    #pragma unroll
    for (int i = 0; i < 32; i += 8) {
        int n = bx + ty + i;
        int k = doff + by + tx;
        int off = ((n >> 3) * KB8 + (k >> 3)) * 64
                + ((n & 7) * 4 + (k & 3)) * 2 + ((k >> 2) & 1);
        dst[off] = tf32r(t[tx][ty + i]);
    }
}

// ---------------------------------------------------------------------------
// Barrier-free tf32 warp-MMA: D[64 x 256] += s_m[64 x 256k] @ W^T.
// Warp tile 32r x 32c: 2 m16 tiles x 4 n8 tiles. d[mt*4+nt][4].
// Per ks-step: 8 LDS.32 (A) + 4 LDG.64 (B, reused 2x) + 8 MMA.
// ---------------------------------------------------------------------------
__device__ __forceinline__ void run_gemm(const float* __restrict__ Wp,
                                         int KB8, int kb0,
                                         const float* s_m, float d[8][4],
                                         int m0, int nb0,
                                         int g, int tig, int lane)
{
    const float* r0 = s_m + (m0 + g) * 260 + tig;        // mt0, row g
    const float* r1 = r0 + 8 * 260;                      // mt0, row g+8
    const float* r2 = r0 + 16 * 260;                     // mt1, row g+16
    const float* r3 = r0 + 24 * 260;                     // mt1, row g+24
    #pragma unroll 1
    for (int c = 0; c < 8; c++) {
        #pragma unroll
        for (int ks = 0; ks < 4; ks++) {
            int kk = c * 32 + ks * 8;
            int kb = kb0 + (kk >> 3);
            uint32_t a00 = __float_as_uint(r0[kk]);
            uint32_t a01 = __float_as_uint(r1[kk]);
            uint32_t a02 = __float_as_uint(r0[kk + 4]);
            uint32_t a03 = __float_as_uint(r1[kk + 4]);
            uint32_t a10 = __float_as_uint(r2[kk]);
            uint32_t a11 = __float_as_uint(r3[kk]);
            uint32_t a12 = __float_as_uint(r2[kk + 4]);
            uint32_t a13 = __float_as_uint(r3[kk + 4]);
            #pragma unroll
            for (int nt = 0; nt < 4; nt++) {
                float2 bv = __ldg(reinterpret_cast<const float2*>(
                                      Wp + ((nb0 + nt) * KB8 + kb) * 64) + lane);
                uint32_t b0 = __float_as_uint(bv.x);
                uint32_t b1 = __float_as_uint(bv.y);
                asm volatile(
                    "mma.sync.aligned.m16n8k8.row.col.f32.tf32.tf32.f32 "
                    "{%0,%1,%2,%3}, {%4,%5,%6,%7}, {%8,%9}, {%0,%1,%2,%3};"
                    : "+f"(d[nt][0]), "+f"(d[nt][1]), "+f"(d[nt][2]), "+f"(d[nt][3])
                    : "r"(a00), "r"(a01), "r"(a02), "r"(a03), "r"(b0), "r"(b1));
                asm volatile(
                    "mma.sync.aligned.m16n8k8.row.col.f32.tf32.tf32.f32 "
                    "{%0,%1,%2,%3}, {%4,%5,%6,%7}, {%8,%9}, {%0,%1,%2,%3};"
                    : "+f"(d[4 + nt][0]), "+f"(d[4 + nt][1]),
                      "+f"(d[4 + nt][2]), "+f"(d[4 + nt][3])
                    : "r"(a10), "r"(a11), "r"(a12), "r"(a13), "r"(b0), "r"(b1));
            }
        }
    }
    __syncthreads();
}

// stage 64 rows x 256 cols from src (row stride 256) into s_m as tf32.
__device__ __forceinline__ void stage_rows(const float* __restrict__ src,
                                           float* s_m, int n0, int tid)
{
    int f4 = (tid & 63) * 4;
    int rb = tid >> 6;
    #pragma unroll
    for (int j = 0; j < 8; j++) {
        int row = j * 8 + rb;
        int node = n0 + row;
        if (node >= NNODE) node = NNODE - 1;
        float4 v = *reinterpret_cast<const float4*>(&src[node * HDIM + f4]);
        v.x = tf32r(v.x); v.y = tf32r(v.y); v.z = tf32r(v.z); v.w = tf32r(v.w);
        *reinterpret_cast<float4*>(&s_m[row * 260 + f4]) = v;
    }
}

// ---------------------------------------------------------------------------
// Precompute kernel (MMA): P = h @ W1a, Q = h @ W1b. Block = 64 nodes.
// ---------------------------------------------------------------------------
extern __shared__ float smm[];

__global__ __launch_bounds__(ETHR, 2)
void precomp_mma(const float* __restrict__ h)
{
    float* s_m = smm + O_M;

    const int tid  = threadIdx.x;
    const int lane = tid & 31;
    const int wid  = tid >> 5;
    const int g    = lane >> 2;
    const int tig  = lane & 3;
    const int m0   = (wid >> 3) * 32;     // 2 M-groups
    const int nb0  = (wid & 7) * 4;       // 8 N-groups, 4 n8-tiles each
    const int n0b  = nb0 * 8;
    const int n0   = blockIdx.x * ET;

    stage_rows(h, s_m, n0, tid);
    __syncthreads();

    float d[8][4];
    #pragma unroll
    for (int s = 0; s < 2; s++) {
        #pragma unroll
        for (int i = 0; i < 8; i++)
            d[i][0] = d[i][1] = d[i][2] = d[i][3] = 0.0f;
        run_gemm(s ? g_W1bt : g_W1at, 32, 0, s_m, d, m0, nb0, g, tig, lane);
        float* out = s ? g_Q : g_P;
        #pragma unroll
        for (int mt = 0; mt < 2; mt++) {
            int r0 = n0 + m0 + 16 * mt + g, r1 = r0 + 8;
            #pragma unroll
            for (int nt = 0; nt < 4; nt++) {
                int f0 = n0b + nt * 8 + 2 * tig;
                int i = mt * 4 + nt;
                if (r0 < NNODE)
                    *reinterpret_cast<float2*>(&out[r0 * HDIM + f0]) =
                        make_float2(d[i][0], d[i][1]);
                if (r1 < NNODE)
                    *reinterpret_cast<float2*>(&out[r1 * HDIM + f0]) =
                        make_float2(d[i][2], d[i][3]);
            }
        }
    }
}

// ---------------------------------------------------------------------------
// Edge kernel: one block = 64 edges, tf32 MMA GEMMs.
// ---------------------------------------------------------------------------
__global__ __launch_bounds__(ETHR, 2)
void edge_mma_kernel(const float* __restrict__ x,
                     const void* __restrict__ ei_raw,
                     const float* __restrict__ W1, const float* __restrict__ b1,
                     const float* __restrict__ b2, const float* __restrict__ cb1,
                     const float* __restrict__ C2)
{
    float* s_m   = smm + O_M;
    int*   s_row = (int*)(smm + O_ROW);
    int*   s_col = (int*)(smm + O_COL);
    float* s_dist = smm + O_DIST;
    float* s_diff = smm + O_DIFF;
    float* s_red  = smm + O_RED;

    const int tid  = threadIdx.x;
    const int lane = tid & 31;
    const int wid  = tid >> 5;
    const int g    = lane >> 2;
    const int tig  = lane & 3;
    const int m0   = (wid >> 3) * 32;
    const int nb0  = (wid & 7) * 4;
    const int n0b  = nb0 * 8;
    const int ng   = wid & 7;
    const int e0   = blockIdx.x * ET;

    if (tid < ET) {
        int e = e0 + tid;
        int r, c;
        if (g_is64) {
            const long long* p = (const long long*)ei_raw;
            r = (int)p[e];
            c = (int)p[NEDGE + e];
        } else {
            const int* p = (const int*)ei_raw;
            r = p[e];
            c = p[NEDGE + e];
        }
        s_row[tid] = r;
        s_col[tid] = c;
        float dx = x[r * 3 + 0] - x[c * 3 + 0];
        float dy = x[r * 3 + 1] - x[c * 3 + 1];
        float dz = x[r * 3 + 2] - x[c * 3 + 2];
        s_diff[tid * 3 + 0] = dx;
        s_diff[tid * 3 + 1] = dy;
        s_diff[tid * 3 + 2] = dz;
        s_dist[tid] = dx * dx + dy * dy + dz * dz;
    }
    __syncthreads();

    // ---- phase B: m = silu(P[row]+Q[col]+dist*w1d+b1) -> s_m (tf32) ----
    {
        int f  = tid & 255;
        int eh = tid >> 8;
        float w1d = W1[512 * HDIM + f];
        float b1f = b1[f];
        #pragma unroll 4
        for (int j = 0; j < 32; j++) {
            int e = eh * 32 + j;
            int r = s_row[e], c = s_col[e];
            float v = g_P[r * HDIM + f] + g_Q[c * HDIM + f] + b1f;
            v = fmaf(s_dist[e], w1d, v);
            s_m[e * 260 + f] = tf32r(silu_f(v));
        }
    }
    __syncthreads();

    float d[8][4];

    // ---- GEMM1: D = m @ W2 ----
    #pragma unroll
    for (int i = 0; i < 8; i++)
        d[i][0] = d[i][1] = d[i][2] = d[i][3] = 0.0f;
    run_gemm(g_W2t, 32, 0, s_m, d, m0, nb0, g, tig, lane);

    // ---- readback1: m_ij = silu(D + b2) -> s_m (exact fp32) ----
    #pragma unroll
    for (int mt = 0; mt < 2; mt++) {
        int er = m0 + 16 * mt + g;
        #pragma unroll
        for (int nt = 0; nt < 4; nt++) {
            int f0 = n0b + nt * 8 + 2 * tig;
            int i = mt * 4 + nt;
            float2 v01 = make_float2(silu_f(d[i][0] + b2[f0]),
                                     silu_f(d[i][1] + b2[f0 + 1]));
            float2 v23 = make_float2(silu_f(d[i][2] + b2[f0]),
                                     silu_f(d[i][3] + b2[f0 + 1]));
            *reinterpret_cast<float2*>(&s_m[er * 260 + f0])       = v01;
            *reinterpret_cast<float2*>(&s_m[(er + 8) * 260 + f0]) = v23;
        }
    }
    __syncthreads();

    // ---- scatter exact m_ij; convert s_m to tf32 for GEMM2 ----
    {
        int f4 = (tid & 63) * 4;
        int eh = tid >> 6;
        #pragma unroll
        for (int j = 0; j < 8; j++) {
            int e = eh * 8 + j;
            float4 v = *reinterpret_cast<float4*>(&s_m[e * 260 + f4]);
            atomicAdd(reinterpret_cast<float4*>(&g_msg[s_col[e] * HDIM + f4]), v);
            v.x = tf32r(v.x); v.y = tf32r(v.y); v.z = tf32r(v.z); v.w = tf32r(v.w);
            *reinterpret_cast<float4*>(&s_m[e * 260 + f4]) = v;
        }
    }
    __syncthreads();

    // ---- GEMM2: D = m_ij @ C1 ----
    #pragma unroll
    for (int i = 0; i < 8; i++)
        d[i][0] = d[i][1] = d[i][2] = d[i][3] = 0.0f;
    run_gemm(g_C1t, 32, 0, s_m, d, m0, nb0, g, tig, lane);

    // ---- readback2: coord_weight = sum_f silu(D + cb1) * C2 ----
    {
        float cw[2][2] = {{0.0f, 0.0f}, {0.0f, 0.0f}};
        #pragma unroll
        for (int mt = 0; mt < 2; mt++) {
            #pragma unroll
            for (int nt = 0; nt < 4; nt++) {
                int f0 = n0b + nt * 8 + 2 * tig;
                int i = mt * 4 + nt;
                float c20 = C2[f0], c21 = C2[f0 + 1];
                float bb0 = cb1[f0], bb1 = cb1[f0 + 1];
                cw[mt][0] += silu_f(d[i][0] + bb0) * c20 + silu_f(d[i][1] + bb1) * c21;
                cw[mt][1] += silu_f(d[i][2] + bb0) * c20 + silu_f(d[i][3] + bb1) * c21;
            }
        }
        #pragma unroll
        for (int mt = 0; mt < 2; mt++) {
            #pragma unroll
            for (int hh = 0; hh < 2; hh++) {
                float v = cw[mt][hh];
                v += __shfl_xor_sync(0xFFFFFFFFu, v, 1);
                v += __shfl_xor_sync(0xFFFFFFFFu, v, 2);
                if (tig == 0)
                    s_red[(m0 + 16 * mt + g + 8 * hh) * 8 + ng] = v;
            }
        }
    }
    __syncthreads();
    if (tid < ET) {
        float w = 0.0f;
        #pragma unroll
        for (int j = 0; j < 8; j++) w += s_red[tid * 8 + j];
        int c = s_col[tid];
        atomicAdd(&g_coord[c * 3 + 0], w * s_diff[tid * 3 + 0]);
        atomicAdd(&g_coord[c * 3 + 1], w * s_diff[tid * 3 + 1]);
        atomicAdd(&g_coord[c * 3 + 2], w * s_diff[tid * 3 + 2]);
    }
}

// ---------------------------------------------------------------------------
// Node kernel (MMA): block = 64 nodes. GEMM1 (K=512, two halves), SiLU,
// GEMM2, residual + LayerNorm epilogue.
// ---------------------------------------------------------------------------
__global__ __launch_bounds__(ETHR, 2)
void node_mma(const float* __restrict__ h,
              const float* __restrict__ nb1, const float* __restrict__ nb2,
              const float* __restrict__ lng, const float* __restrict__ lnb,
              float* __restrict__ out_h)
{
    float* s_m  = smm + O_M;
    float* s_r1 = smm + O_R1;
    float* s_r2 = smm + O_R2;
    float* s_mu = smm + O_MU;
    float* s_rs = smm + O_RS;

    const int tid  = threadIdx.x;
    const int lane = tid & 31;
    const int wid  = tid >> 5;
    const int g    = lane >> 2;
    const int tig  = lane & 3;
    const int m0   = (wid >> 3) * 32;
    const int nb0  = (wid & 7) * 4;
    const int n0b  = nb0 * 8;
    const int ng   = wid & 7;
    const int n0   = blockIdx.x * ET;

    float d[8][4];

    // ---- GEMM1: u_pre = [h | msg] @ NW1 + nb1  (K = 512, two halves) ----
    #pragma unroll
    for (int mt = 0; mt < 2; mt++)
        #pragma unroll
        for (int nt = 0; nt < 4; nt++) {
            int f0 = n0b + nt * 8 + 2 * tig;
            int i = mt * 4 + nt;
            d[i][0] = nb1[f0]; d[i][1] = nb1[f0 + 1];
            d[i][2] = d[i][0]; d[i][3] = d[i][1];
        }
    stage_rows(h, s_m, n0, tid);
    __syncthreads();
    run_gemm(g_NW1t, 64, 0, s_m, d, m0, nb0, g, tig, lane);

    stage_rows(g_msg, s_m, n0, tid);
    __syncthreads();
    run_gemm(g_NW1t, 64, 32, s_m, d, m0, nb0, g, tig, lane);

    // u = silu(.) -> s_m (tf32) for GEMM2
    #pragma unroll
    for (int mt = 0; mt < 2; mt++) {
        int r = m0 + 16 * mt + g;
        #pragma unroll
        for (int nt = 0; nt < 4; nt++) {
            int f0 = n0b + nt * 8 + 2 * tig;
            int i = mt * 4 + nt;
            float2 v01 = make_float2(tf32r(silu_f(d[i][0])), tf32r(silu_f(d[i][1])));
            float2 v23 = make_float2(tf32r(silu_f(d[i][2])), tf32r(silu_f(d[i][3])));
            *reinterpret_cast<float2*>(&s_m[r * 260 + f0])       = v01;
            *reinterpret_cast<float2*>(&s_m[(r + 8) * 260 + f0]) = v23;
        }
    }
    __syncthreads();

    // ---- GEMM2: y = u @ NW2 + nb2 + h ----
    #pragma unroll
    for (int mt = 0; mt < 2; mt++)
        #pragma unroll
        for (int nt = 0; nt < 4; nt++) {
            int f0 = n0b + nt * 8 + 2 * tig;
            int i = mt * 4 + nt;
            d[i][0] = nb2[f0]; d[i][1] = nb2[f0 + 1];
            d[i][2] = d[i][0]; d[i][3] = d[i][1];
        }
    run_gemm(g_NW2t, 32, 0, s_m, d, m0, nb0, g, tig, lane);

    // residual + LayerNorm partial sums (per thread: 4 row variants)
    float s1[2][2] = {{0, 0}, {0, 0}}, s2[2][2] = {{0, 0}, {0, 0}};
    #pragma unroll
    for (int mt = 0; mt < 2; mt++) {
        int gr0 = n0 + m0 + 16 * mt + g, gr1 = gr0 + 8;
        #pragma unroll
        for (int nt = 0; nt < 4; nt++) {
            int f0 = n0b + nt * 8 + 2 * tig;
            int i = mt * 4 + nt;
            float2 h0 = (gr0 < NNODE)
                ? *reinterpret_cast<const float2*>(&h[gr0 * HDIM + f0])
                : make_float2(0.0f, 0.0f);
            float2 h1 = (gr1 < NNODE)
                ? *reinterpret_cast<const float2*>(&h[gr1 * HDIM + f0])
                : make_float2(0.0f, 0.0f);
            d[i][0] += h0.x; d[i][1] += h0.y;
            d[i][2] += h1.x; d[i][3] += h1.y;
            s1[mt][0] += d[i][0] + d[i][1];
            s2[mt][0] += d[i][0] * d[i][0] + d[i][1] * d[i][1];
            s1[mt][1] += d[i][2] + d[i][3];
            s2[mt][1] += d[i][2] * d[i][2] + d[i][3] * d[i][3];
        }
    }
    #pragma unroll
    for (int mt = 0; mt < 2; mt++)
        #pragma unroll
        for (int hh = 0; hh < 2; hh++) {
            float v1 = s1[mt][hh], v2 = s2[mt][hh];
            v1 += __shfl_xor_sync(0xFFFFFFFFu, v1, 1);
            v1 += __shfl_xor_sync(0xFFFFFFFFu, v1, 2);
            v2 += __shfl_xor_sync(0xFFFFFFFFu, v2, 1);
            v2 += __shfl_xor_sync(0xFFFFFFFFu, v2, 2);
            if (tig == 0) {
                int row = m0 + 16 * mt + g + 8 * hh;
                s_r1[row * 8 + ng] = v1;
                s_r2[row * 8 + ng] = v2;
            }
        }
    __syncthreads();
    if (tid < ET) {
        float S1 = 0.0f, S2 = 0.0f;
        #pragma unroll
        for (int j = 0; j < 8; j++) { S1 += s_r1[tid * 8 + j]; S2 += s_r2[tid * 8 + j]; }
        float mu  = S1 * (1.0f / HDIM);
        float var = S2 * (1.0f / HDIM) - mu * mu;
        s_mu[tid] = mu;
        s_rs[tid] = rsqrtf(var + LN_EPS);
    }
    __syncthreads();
    #pragma unroll
    for (int mt = 0; mt < 2; mt++) {
        int row0 = m0 + 16 * mt + g;
        int gr0 = n0 + row0, gr1 = gr0 + 8;
        float mu0 = s_mu[row0],     rs0 = s_rs[row0];
        float mu1 = s_mu[row0 + 8], rs1 = s_rs[row0 + 8];
        #pragma unroll
        for (int nt = 0; nt < 4; nt++) {
            int f0 = n0b + nt * 8 + 2 * tig;
            int i = mt * 4 + nt;
            float g0 = lng[f0], g1 = lng[f0 + 1];
            float b0 = lnb[f0], b1v = lnb[f0 + 1];
            if (gr0 < NNODE)
                *reinterpret_cast<float2*>(&out_h[gr0 * HDIM + f0]) =
                    make_float2((d[i][0] - mu0) * rs0 * g0 + b0,
                                (d[i][1] - mu0) * rs0 * g1 + b1v);
            if (gr1 < NNODE)
                *reinterpret_cast<float2*>(&out_h[gr1 * HDIM + f0]) =
                    make_float2((d[i][2] - mu1) * rs1 * g0 + b0,
                                (d[i][3] - mu1) * rs1 * g1 + b1v);
        }
    }
}

// ---------------------------------------------------------------------------
__global__ void xnew_kernel(const float* __restrict__ x, float* __restrict__ out_x) {
    int i = blockIdx.x * blockDim.x + threadIdx.x;
    if (i < NNODE * 3) out_x[i] = x[i] + g_coord[i];
}

// ---------------------------------------------------------------------------
extern "C" void kernel_launch(void* const* d_in, const int* in_sizes, int n_in,
                              void* d_out, int out_size)
{
    const float* h    = (const float*)d_in[0];
    const float* x    = (const float*)d_in[1];
    const void*  ei   = d_in[2];
    const float* e_w1 = (const float*)d_in[3];
    const float* e_b1 = (const float*)d_in[4];
    const float* e_w2 = (const float*)d_in[5];
    const float* e_b2 = (const float*)d_in[6];
    const float* c_w1 = (const float*)d_in[7];
    const float* c_b1 = (const float*)d_in[8];
    const float* c_w2 = (const float*)d_in[9];
    const float* n_w1 = (const float*)d_in[10];
    const float* n_b1 = (const float*)d_in[11];
    const float* n_w2 = (const float*)d_in[12];
    const float* n_b2 = (const float*)d_in[13];
    const float* ln_g = (const float*)d_in[14];
    const float* ln_b = (const float*)d_in[15];
    float* out = (float*)d_out;

    cudaFuncSetAttribute(precomp_mma,     cudaFuncAttributeMaxDynamicSharedMemorySize, MMA_SMEM);
    cudaFuncSetAttribute(edge_mma_kernel, cudaFuncAttributeMaxDynamicSharedMemorySize, MMA_SMEM);
    cudaFuncSetAttribute(node_mma,        cudaFuncAttributeMaxDynamicSharedMemorySize, MMA_SMEM);

    const int nblk = (NNODE + ET - 1) / ET;

    detect_kernel<<<1, 32>>>((const unsigned*)ei);
    zero_kernel<<<512, 256>>>();
    transpose_kernel<<<dim3(8, 8, 7), dim3(32, 8)>>>(e_w2, c_w1, e_w1, n_w1, n_w2);
    precomp_mma<<<nblk, ETHR, MMA_SMEM>>>(h);
    edge_mma_kernel<<<NEDGE / ET, ETHR, MMA_SMEM>>>(x, ei, e_w1, e_b1,
                                                    e_b2, c_b1, c_w2);
    node_mma<<<nblk, ETHR, MMA_SMEM>>>(h, n_b1, n_b2, ln_g, ln_b, out);
    xnew_kernel<<<(NNODE * 3 + 255) / 256, 256>>>(x, out + NNODE * HDIM);
}